// round 8
// baseline (speedup 1.0000x reference)
#include <cuda_runtime.h>
#include <cstdint>

#define NMAX 100000
#define EMAX 1600000
#define HID  128

// Scratch (static device globals — allocation-free per harness rules).
// g_cnt is zero-initialized at load; add_off re-zeros it every run so each
// graph replay sees cnt==0 at hist_kernel.
__device__ float g_norm[NMAX];
__device__ int   g_cnt[NMAX];
__device__ int   g_rowptr[NMAX + 1];
__device__ int   g_cursor[NMAX];
__device__ int   g_bsums[128];
__device__ int   g_csr[EMAX];
__device__ float g_t1[(size_t)NMAX * HID];
__device__ float g_t2[(size_t)NMAX * HID];
__device__ float g_h1[(size_t)NMAX * HID];
__device__ float g_h2[(size_t)NMAX * HID];

// ---------------------------------------------------------------------------
// degree histogram
// ---------------------------------------------------------------------------
__global__ void hist_kernel(const int* __restrict__ dst, int E, int* __restrict__ cnt) {
    int i = blockIdx.x * blockDim.x + threadIdx.x;
    if (i < E) atomicAdd(&cnt[dst[i]], 1);
}

// ---------------------------------------------------------------------------
// exclusive scan of cnt -> rowptr (1024 elems/block); also computes norm
// ---------------------------------------------------------------------------
__global__ void scan_block(const int* __restrict__ cnt, int* __restrict__ out,
                           int* __restrict__ bsums, float* __restrict__ norm, int N) {
    __shared__ int ss[256];
    const int tid  = threadIdx.x;
    const int base = blockIdx.x * 1024 + tid * 4;
    int local[4];
#pragma unroll
    for (int i = 0; i < 4; i++) {
        int g = base + i;
        local[i] = (g < N) ? cnt[g] : 0;
        if (g < N) norm[g] = rsqrtf(fmaxf((float)local[i], 1.0f));
    }
    int tsum = local[0] + local[1] + local[2] + local[3];
    ss[tid] = tsum;
    __syncthreads();
#pragma unroll
    for (int off = 1; off < 256; off <<= 1) {
        int v = (tid >= off) ? ss[tid - off] : 0;
        __syncthreads();
        ss[tid] += v;
        __syncthreads();
    }
    int run = ss[tid] - tsum;   // exclusive
#pragma unroll
    for (int i = 0; i < 4; i++) {
        int g = base + i;
        if (g < N) out[g] = run;
        run += local[i];
    }
    if (tid == 255) bsums[blockIdx.x] = ss[255];
}

// add block offsets (computing the bsums prefix in-block), init cursor,
// and re-zero cnt for the next graph replay.
__global__ void add_off(int* __restrict__ rowptr, int* __restrict__ cursor,
                        int* __restrict__ cnt, const int* __restrict__ bsums,
                        int N, int E, int nb) {
    __shared__ int ss[256];
    const int tid = threadIdx.x;
    int v = (tid < nb && tid < blockIdx.x) ? bsums[tid] : 0;
    ss[tid] = v;
    __syncthreads();
#pragma unroll
    for (int off = 128; off > 0; off >>= 1) {
        if (tid < off) ss[tid] += ss[tid + off];
        __syncthreads();
    }
    const int o = ss[0];
    int g = blockIdx.x * 1024 + tid * 4;
#pragma unroll
    for (int i = 0; i < 4; i++) {
        if (g + i < N) {
            int val = rowptr[g + i] + o;
            rowptr[g + i] = val;
            cursor[g + i] = val;
            cnt[g + i]    = 0;      // restore invariant for next replay
        }
    }
    if (blockIdx.x == 0 && tid == 0) rowptr[N] = E;
}

__global__ void scatter_kernel(const int* __restrict__ src, const int* __restrict__ dst,
                               int E, int* __restrict__ cursor, int* __restrict__ csr) {
    int e = blockIdx.x * blockDim.x + threadIdx.x;
    if (e < E) {
        int d = dst[e];
        int pos = atomicAdd(&cursor[d], 1);
        csr[pos] = src[e];
    }
}

// ---------------------------------------------------------------------------
// pull propagation with software-pipelined index chain:
// out[d] = norm[d] * sum_{s in row(d)} norm[s]*h[s]
// Group i+1's csr/norm broadcast loads issue while group i's gathers fly.
// ---------------------------------------------------------------------------
__global__ __launch_bounds__(256)
void prop_pull128(const float* __restrict__ h, const float* __restrict__ norm,
                  const int* __restrict__ rowptr, const int* __restrict__ csr,
                  float* __restrict__ out, int N) {
    const int warp = (blockIdx.x * blockDim.x + threadIdx.x) >> 5;
    const int lane = threadIdx.x & 31;
    if (warp >= N) return;
    const int beg = __ldg(rowptr + warp);
    const int end = __ldg(rowptr + warp + 1);
    const float4* __restrict__ h4 = reinterpret_cast<const float4*>(h);

    float4 acc = make_float4(0.f, 0.f, 0.f, 0.f);
    const int cnt4 = (end - beg) >> 2;
    int e = beg;

    if (cnt4 > 0) {
        int   s0 = __ldg(csr + e + 0), s1 = __ldg(csr + e + 1);
        int   s2 = __ldg(csr + e + 2), s3 = __ldg(csr + e + 3);
        float n0 = __ldg(norm + s0),  n1 = __ldg(norm + s1);
        float n2 = __ldg(norm + s2),  n3 = __ldg(norm + s3);
        for (int g = 0; g < cnt4; ++g) {
            // gathers for current group (independent, MLP 4)
            float4 v0 = __ldg(h4 + (size_t)s0 * 32 + lane);
            float4 v1 = __ldg(h4 + (size_t)s1 * 32 + lane);
            float4 v2 = __ldg(h4 + (size_t)s2 * 32 + lane);
            float4 v3 = __ldg(h4 + (size_t)s3 * 32 + lane);
            // prefetch next group's indices + norms (predicated)
            const int  ne   = e + 4;
            const bool more = (g + 1 < cnt4);
            int   t0 = more ? __ldg(csr + ne + 0) : 0;
            int   t1 = more ? __ldg(csr + ne + 1) : 0;
            int   t2 = more ? __ldg(csr + ne + 2) : 0;
            int   t3 = more ? __ldg(csr + ne + 3) : 0;
            float m0 = more ? __ldg(norm + t0) : 0.f;
            float m1 = more ? __ldg(norm + t1) : 0.f;
            float m2 = more ? __ldg(norm + t2) : 0.f;
            float m3 = more ? __ldg(norm + t3) : 0.f;
            // accumulate current
            acc.x += v0.x * n0 + v1.x * n1 + v2.x * n2 + v3.x * n3;
            acc.y += v0.y * n0 + v1.y * n1 + v2.y * n2 + v3.y * n3;
            acc.z += v0.z * n0 + v1.z * n1 + v2.z * n2 + v3.z * n3;
            acc.w += v0.w * n0 + v1.w * n1 + v2.w * n2 + v3.w * n3;
            s0 = t0; s1 = t1; s2 = t2; s3 = t3;
            n0 = m0; n1 = m1; n2 = m2; n3 = m3;
            e = ne;
        }
    }
    for (; e < end; ++e) {
        int s = __ldg(csr + e);
        float n = __ldg(norm + s);
        float4 v = __ldg(h4 + (size_t)s * 32 + lane);
        acc.x += v.x * n; acc.y += v.y * n; acc.z += v.z * n; acc.w += v.w * n;
    }
    const float nd = __ldg(norm + warp);
    acc.x *= nd; acc.y *= nd; acc.z *= nd; acc.w *= nd;
    reinterpret_cast<float4*>(out)[(size_t)warp * 32 + lane] = acc;
}

__global__ __launch_bounds__(256)
void prop_pull32(const float* __restrict__ h, const float* __restrict__ norm,
                 const int* __restrict__ rowptr, const int* __restrict__ csr,
                 float* __restrict__ out, int N) {
    const int t    = blockIdx.x * blockDim.x + threadIdx.x;
    const int node = t >> 3;
    const int lane = t & 7;
    if (node >= N) return;
    const int beg = __ldg(rowptr + node);
    const int end = __ldg(rowptr + node + 1);
    const float4* __restrict__ h4 = reinterpret_cast<const float4*>(h);

    float4 acc = make_float4(0.f, 0.f, 0.f, 0.f);
    const int cnt4 = (end - beg) >> 2;
    int e = beg;

    if (cnt4 > 0) {
        int   s0 = __ldg(csr + e + 0), s1 = __ldg(csr + e + 1);
        int   s2 = __ldg(csr + e + 2), s3 = __ldg(csr + e + 3);
        float n0 = __ldg(norm + s0),  n1 = __ldg(norm + s1);
        float n2 = __ldg(norm + s2),  n3 = __ldg(norm + s3);
        for (int g = 0; g < cnt4; ++g) {
            float4 v0 = __ldg(h4 + (size_t)s0 * 8 + lane);
            float4 v1 = __ldg(h4 + (size_t)s1 * 8 + lane);
            float4 v2 = __ldg(h4 + (size_t)s2 * 8 + lane);
            float4 v3 = __ldg(h4 + (size_t)s3 * 8 + lane);
            const int  ne   = e + 4;
            const bool more = (g + 1 < cnt4);
            int   t0 = more ? __ldg(csr + ne + 0) : 0;
            int   t1 = more ? __ldg(csr + ne + 1) : 0;
            int   t2 = more ? __ldg(csr + ne + 2) : 0;
            int   t3 = more ? __ldg(csr + ne + 3) : 0;
            float m0 = more ? __ldg(norm + t0) : 0.f;
            float m1 = more ? __ldg(norm + t1) : 0.f;
            float m2 = more ? __ldg(norm + t2) : 0.f;
            float m3 = more ? __ldg(norm + t3) : 0.f;
            acc.x += v0.x * n0 + v1.x * n1 + v2.x * n2 + v3.x * n3;
            acc.y += v0.y * n0 + v1.y * n1 + v2.y * n2 + v3.y * n3;
            acc.z += v0.z * n0 + v1.z * n1 + v2.z * n2 + v3.z * n3;
            acc.w += v0.w * n0 + v1.w * n1 + v2.w * n2 + v3.w * n3;
            s0 = t0; s1 = t1; s2 = t2; s3 = t3;
            n0 = m0; n1 = m1; n2 = m2; n3 = m3;
            e = ne;
        }
    }
    for (; e < end; ++e) {
        int s = __ldg(csr + e);
        float n = __ldg(norm + s);
        float4 v = __ldg(h4 + (size_t)s * 8 + lane);
        acc.x += v.x * n; acc.y += v.y * n; acc.z += v.z * n; acc.w += v.w * n;
    }
    const float nd = __ldg(norm + node);
    acc.x *= nd; acc.y *= nd; acc.z *= nd; acc.w *= nd;
    reinterpret_cast<float4*>(out)[(size_t)node * 8 + lane] = acc;
}

// ---------------------------------------------------------------------------
// TF32 tensor-core fused GEMM (R4-proven schedule):
// out = relu(H0@W[0:DIN] + H1@W[DIN:2DIN] + H2@W[2DIN:3DIN] + b)
// ---------------------------------------------------------------------------
__device__ __forceinline__ uint32_t f2tf32(float f) {
    uint32_t u;
    asm("cvt.rna.tf32.f32 %0, %1;" : "=r"(u) : "f"(f));
    return u;
}

__device__ __forceinline__ void mma_tf32(float c[4], const uint32_t a[4], const uint32_t b[2]) {
    asm volatile(
        "mma.sync.aligned.m16n8k8.row.col.f32.tf32.tf32.f32 "
        "{%0,%1,%2,%3}, {%4,%5,%6,%7}, {%8,%9}, {%0,%1,%2,%3};"
        : "+f"(c[0]), "+f"(c[1]), "+f"(c[2]), "+f"(c[3])
        : "r"(a[0]), "r"(a[1]), "r"(a[2]), "r"(a[3]), "r"(b[0]), "r"(b[1]));
}

template <int DIN>
__global__ __launch_bounds__(256)
void gemm3_tf32(const float* __restrict__ H0, const float* __restrict__ H1,
                const float* __restrict__ H2, const float* __restrict__ W,
                const float* __restrict__ bias, float* __restrict__ out, int N) {
    __shared__ __align__(16) uint32_t As[32][132];   // As[k][m] (tf32 bits)
    __shared__ __align__(16) uint32_t Bs[32][128];   // Bs[k][n] (tf32 bits)

    const int tid     = threadIdx.x;
    const int wid     = tid >> 5;
    const int lane    = tid & 31;
    const int warp_m  = wid & 3;
    const int warp_n  = wid >> 2;
    const int groupID = lane >> 2;
    const int tig     = lane & 3;
    const int m0      = blockIdx.x * 128;

    float c[2][8][4];
#pragma unroll
    for (int mt = 0; mt < 2; mt++)
#pragma unroll
        for (int nt = 0; nt < 8; nt++)
#pragma unroll
            for (int i = 0; i < 4; i++) c[mt][nt][i] = 0.0f;

    const float* srcs[3] = {H0, H1, H2};

    const int aRow = tid >> 3;
    const int aCol = (tid & 7) * 4;
    const int bRow = tid >> 5;
    const int bCol = (tid & 31) * 4;

    for (int part = 0; part < 3; ++part) {
        const float* __restrict__ Hp = srcs[part];
        for (int k0 = 0; k0 < DIN; k0 += 32) {
#pragma unroll
            for (int r = 0; r < 4; ++r) {
                int row = m0 + r * 32 + aRow;
                float4 v = make_float4(0.f, 0.f, 0.f, 0.f);
                if (row < N)
                    v = __ldg(reinterpret_cast<const float4*>(Hp + (size_t)row * DIN + k0 + aCol));
                As[aCol + 0][r * 32 + aRow] = f2tf32(v.x);
                As[aCol + 1][r * 32 + aRow] = f2tf32(v.y);
                As[aCol + 2][r * 32 + aRow] = f2tf32(v.z);
                As[aCol + 3][r * 32 + aRow] = f2tf32(v.w);
            }
#pragma unroll
            for (int r = 0; r < 4; ++r) {
                int krow = r * 8 + bRow;
                float4 v = __ldg(reinterpret_cast<const float4*>(
                    W + (size_t)(part * DIN + k0 + krow) * 128 + bCol));
                uint4 u;
                u.x = f2tf32(v.x); u.y = f2tf32(v.y);
                u.z = f2tf32(v.z); u.w = f2tf32(v.w);
                *reinterpret_cast<uint4*>(&Bs[krow][bCol]) = u;
            }
            __syncthreads();

#pragma unroll
            for (int kk = 0; kk < 4; ++kk) {
                const int kb = kk * 8;
                uint32_t a[2][4];
#pragma unroll
                for (int mt = 0; mt < 2; mt++) {
                    int m = warp_m * 32 + mt * 16 + groupID;
                    a[mt][0] = As[kb + tig][m];
                    a[mt][1] = As[kb + tig][m + 8];
                    a[mt][2] = As[kb + tig + 4][m];
                    a[mt][3] = As[kb + tig + 4][m + 8];
                }
                uint32_t b[8][2];
#pragma unroll
                for (int nt = 0; nt < 8; nt++) {
                    int n = warp_n * 64 + nt * 8 + groupID;
                    b[nt][0] = Bs[kb + tig][n];
                    b[nt][1] = Bs[kb + tig + 4][n];
                }
#pragma unroll
                for (int mt = 0; mt < 2; mt++)
#pragma unroll
                    for (int nt = 0; nt < 8; nt++)
                        mma_tf32(c[mt][nt], a[mt], b[nt]);
            }
            __syncthreads();
        }
    }

#pragma unroll
    for (int nt = 0; nt < 8; nt++) {
        int col = warp_n * 64 + nt * 8 + tig * 2;
        float2 bv = __ldg(reinterpret_cast<const float2*>(bias + col));
#pragma unroll
        for (int mt = 0; mt < 2; mt++) {
            int row0 = m0 + warp_m * 32 + mt * 16 + groupID;
            if (row0 < N) {
                float2 o;
                o.x = fmaxf(c[mt][nt][0] + bv.x, 0.f);
                o.y = fmaxf(c[mt][nt][1] + bv.y, 0.f);
                *reinterpret_cast<float2*>(out + (size_t)row0 * 128 + col) = o;
            }
            int row1 = row0 + 8;
            if (row1 < N) {
                float2 o;
                o.x = fmaxf(c[mt][nt][2] + bv.x, 0.f);
                o.y = fmaxf(c[mt][nt][3] + bv.y, 0.f);
                *reinterpret_cast<float2*>(out + (size_t)row1 * 128 + col) = o;
            }
        }
    }
}

// ---------------------------------------------------------------------------
// launch
// ---------------------------------------------------------------------------
extern "C" void kernel_launch(void* const* d_in, const int* in_sizes, int n_in,
                              void* d_out, int out_size) {
    const float* x   = (const float*)d_in[0];
    const int*   src = (const int*)d_in[1];
    const int*   dst = (const int*)d_in[2];
    const float* W1  = (const float*)d_in[3];
    const float* b1  = (const float*)d_in[4];
    const float* W2  = (const float*)d_in[5];
    const float* b2  = (const float*)d_in[6];
    const float* W3  = (const float*)d_in[7];
    const float* b3  = (const float*)d_in[8];
    float* out = (float*)d_out;

    const int N = in_sizes[0] / 32;
    const int E = in_sizes[1];

    float *p_norm, *p_t1, *p_t2, *p_h1, *p_h2;
    int *p_cnt, *p_rowptr, *p_cursor, *p_bsums, *p_csr;
    cudaGetSymbolAddress((void**)&p_norm,   g_norm);
    cudaGetSymbolAddress((void**)&p_cnt,    g_cnt);
    cudaGetSymbolAddress((void**)&p_rowptr, g_rowptr);
    cudaGetSymbolAddress((void**)&p_cursor, g_cursor);
    cudaGetSymbolAddress((void**)&p_bsums,  g_bsums);
    cudaGetSymbolAddress((void**)&p_csr,    g_csr);
    cudaGetSymbolAddress((void**)&p_t1,     g_t1);
    cudaGetSymbolAddress((void**)&p_t2,     g_t2);
    cudaGetSymbolAddress((void**)&p_h1,     g_h1);
    cudaGetSymbolAddress((void**)&p_h2,     g_h2);

    const int TB = 256;
    const int nb = (N + 1023) / 1024;

    // degree + norm + CSR build (cnt re-zeroed by add_off each replay)
    hist_kernel<<<(E + TB - 1) / TB, TB>>>(dst, E, p_cnt);
    scan_block<<<nb, 256>>>(p_cnt, p_rowptr, p_bsums, p_norm, N);
    add_off<<<nb, 256>>>(p_rowptr, p_cursor, p_cnt, p_bsums, N, E, nb);
    scatter_kernel<<<(E + TB - 1) / TB, TB>>>(src, dst, E, p_cursor, p_csr);

    const int g128 = (N * 32 + TB - 1) / TB;   // warp per node
    const int g32  = (N * 8 + TB - 1) / TB;    // 8 lanes per node
    const int gg   = (N + 127) / 128;

    // ---- layer 1 (din = 32) ----
    prop_pull32<<<g32, TB>>>(x,    p_norm, p_rowptr, p_csr, p_t1, N);
    prop_pull32<<<g32, TB>>>(p_t1, p_norm, p_rowptr, p_csr, p_t2, N);
    gemm3_tf32<32><<<gg, 256>>>(x, p_t1, p_t2, W1, b1, p_h1, N);

    // ---- layer 2 (din = 128) ----
    prop_pull128<<<g128, TB>>>(p_h1, p_norm, p_rowptr, p_csr, p_t1, N);
    prop_pull128<<<g128, TB>>>(p_t1, p_norm, p_rowptr, p_csr, p_t2, N);
    gemm3_tf32<128><<<gg, 256>>>(p_h1, p_t1, p_t2, W2, b2, p_h2, N);

    // ---- layer 3 (din = 128) ----
    prop_pull128<<<g128, TB>>>(p_h2, p_norm, p_rowptr, p_csr, p_t1, N);
    prop_pull128<<<g128, TB>>>(p_t1, p_norm, p_rowptr, p_csr, p_t2, N);
    gemm3_tf32<128><<<gg, 256>>>(p_h2, p_t1, p_t2, W3, b3, out, N);
}

// round 9
// speedup vs baseline: 1.1964x; 1.1964x over previous
#include <cuda_runtime.h>
#include <cuda_fp16.h>
#include <cstdint>

#define NMAX 100000
#define EMAX 1600000
#define HID  128

// Scratch (static device globals — allocation-free per harness rules).
// g_cnt zero-init at load; add_off re-zeros each run (graph-replay safe).
__device__ float  g_norm[NMAX];
__device__ int    g_cnt[NMAX];
__device__ int    g_rowptr[NMAX + 1];
__device__ int    g_cursor[NMAX];
__device__ int    g_bsums[128];
__device__ int    g_csr[EMAX];
__device__ __half g_xh[(size_t)NMAX * 32];
__device__ __half g_t1[(size_t)NMAX * HID];
__device__ __half g_t2[(size_t)NMAX * HID];
__device__ __half g_h1[(size_t)NMAX * HID];
__device__ __half g_h2[(size_t)NMAX * HID];

// ---------------------------------------------------------------------------
// x (fp32) -> xh (fp16)
// ---------------------------------------------------------------------------
__global__ void f2h_kernel(const float* __restrict__ x, __half* __restrict__ xh, int n4) {
    int i = blockIdx.x * blockDim.x + threadIdx.x;
    if (i < n4) {
        float4 v = __ldg(reinterpret_cast<const float4*>(x) + i);
        __half2 a = __floats2half2_rn(v.x, v.y);
        __half2 b = __floats2half2_rn(v.z, v.w);
        uint2 u;
        u.x = *reinterpret_cast<uint32_t*>(&a);
        u.y = *reinterpret_cast<uint32_t*>(&b);
        reinterpret_cast<uint2*>(xh)[i] = u;
    }
}

// ---------------------------------------------------------------------------
// degree histogram
// ---------------------------------------------------------------------------
__global__ void hist_kernel(const int* __restrict__ dst, int E, int* __restrict__ cnt) {
    int i = blockIdx.x * blockDim.x + threadIdx.x;
    if (i < E) atomicAdd(&cnt[dst[i]], 1);
}

// ---------------------------------------------------------------------------
// exclusive scan of cnt -> rowptr (1024 elems/block); also computes norm
// ---------------------------------------------------------------------------
__global__ void scan_block(const int* __restrict__ cnt, int* __restrict__ out,
                           int* __restrict__ bsums, float* __restrict__ norm, int N) {
    __shared__ int ss[256];
    const int tid  = threadIdx.x;
    const int base = blockIdx.x * 1024 + tid * 4;
    int local[4];
#pragma unroll
    for (int i = 0; i < 4; i++) {
        int g = base + i;
        local[i] = (g < N) ? cnt[g] : 0;
        if (g < N) norm[g] = rsqrtf(fmaxf((float)local[i], 1.0f));
    }
    int tsum = local[0] + local[1] + local[2] + local[3];
    ss[tid] = tsum;
    __syncthreads();
#pragma unroll
    for (int off = 1; off < 256; off <<= 1) {
        int v = (tid >= off) ? ss[tid - off] : 0;
        __syncthreads();
        ss[tid] += v;
        __syncthreads();
    }
    int run = ss[tid] - tsum;   // exclusive
#pragma unroll
    for (int i = 0; i < 4; i++) {
        int g = base + i;
        if (g < N) out[g] = run;
        run += local[i];
    }
    if (tid == 255) bsums[blockIdx.x] = ss[255];
}

// add block offsets (bsums prefix computed in-block), init cursor, re-zero cnt.
__global__ void add_off(int* __restrict__ rowptr, int* __restrict__ cursor,
                        int* __restrict__ cnt, const int* __restrict__ bsums,
                        int N, int E, int nb) {
    __shared__ int ss[256];
    const int tid = threadIdx.x;
    int v = (tid < nb && tid < blockIdx.x) ? bsums[tid] : 0;
    ss[tid] = v;
    __syncthreads();
#pragma unroll
    for (int off = 128; off > 0; off >>= 1) {
        if (tid < off) ss[tid] += ss[tid + off];
        __syncthreads();
    }
    const int o = ss[0];
    int g = blockIdx.x * 1024 + tid * 4;
#pragma unroll
    for (int i = 0; i < 4; i++) {
        if (g + i < N) {
            int val = rowptr[g + i] + o;
            rowptr[g + i] = val;
            cursor[g + i] = val;
            cnt[g + i]    = 0;
        }
    }
    if (blockIdx.x == 0 && tid == 0) rowptr[N] = E;
}

__global__ void scatter_kernel(const int* __restrict__ src, const int* __restrict__ dst,
                               int E, int* __restrict__ cursor, int* __restrict__ csr) {
    int e = blockIdx.x * blockDim.x + threadIdx.x;
    if (e < E) {
        int d = dst[e];
        int pos = atomicAdd(&cursor[d], 1);
        csr[pos] = src[e];
    }
}

// ---------------------------------------------------------------------------
// fp16 gather helpers
// ---------------------------------------------------------------------------
__device__ __forceinline__ float4 ld_h4(const uint2* p) {
    uint2 u = __ldg(p);
    __half2 a = *reinterpret_cast<__half2*>(&u.x);
    __half2 b = *reinterpret_cast<__half2*>(&u.y);
    float2 fa = __half22float2(a);
    float2 fb = __half22float2(b);
    return make_float4(fa.x, fa.y, fb.x, fb.y);
}

__device__ __forceinline__ uint2 st_h4(float4 v) {
    __half2 a = __floats2half2_rn(v.x, v.y);
    __half2 b = __floats2half2_rn(v.z, v.w);
    uint2 u;
    u.x = *reinterpret_cast<uint32_t*>(&a);
    u.y = *reinterpret_cast<uint32_t*>(&b);
    return u;
}

// ---------------------------------------------------------------------------
// pull propagation (R4 loop structure, fp16 rows, fp32 accumulate):
// out[d] = norm[d] * sum_{s in row(d)} norm[s]*h[s]
// D=128: warp per node, lane covers 4 dims (8B uint2 per gather).
// ---------------------------------------------------------------------------
__global__ __launch_bounds__(256)
void prop_pull128(const __half* __restrict__ h, const float* __restrict__ norm,
                  const int* __restrict__ rowptr, const int* __restrict__ csr,
                  __half* __restrict__ out, int N) {
    int warp = (blockIdx.x * blockDim.x + threadIdx.x) >> 5;
    int lane = threadIdx.x & 31;
    if (warp >= N) return;
    int beg = __ldg(rowptr + warp), end = __ldg(rowptr + warp + 1);
    const uint2* __restrict__ hv = reinterpret_cast<const uint2*>(h);   // 4 halfs each
    float4 acc = make_float4(0.f, 0.f, 0.f, 0.f);
    int e = beg;
    for (; e + 4 <= end; e += 4) {
        int s0 = __ldg(csr + e), s1 = __ldg(csr + e + 1);
        int s2 = __ldg(csr + e + 2), s3 = __ldg(csr + e + 3);
        float n0 = __ldg(norm + s0), n1 = __ldg(norm + s1);
        float n2 = __ldg(norm + s2), n3 = __ldg(norm + s3);
        float4 v0 = ld_h4(hv + (size_t)s0 * 32 + lane);
        float4 v1 = ld_h4(hv + (size_t)s1 * 32 + lane);
        float4 v2 = ld_h4(hv + (size_t)s2 * 32 + lane);
        float4 v3 = ld_h4(hv + (size_t)s3 * 32 + lane);
        acc.x += v0.x * n0 + v1.x * n1 + v2.x * n2 + v3.x * n3;
        acc.y += v0.y * n0 + v1.y * n1 + v2.y * n2 + v3.y * n3;
        acc.z += v0.z * n0 + v1.z * n1 + v2.z * n2 + v3.z * n3;
        acc.w += v0.w * n0 + v1.w * n1 + v2.w * n2 + v3.w * n3;
    }
    for (; e < end; ++e) {
        int s = __ldg(csr + e);
        float n = __ldg(norm + s);
        float4 v = ld_h4(hv + (size_t)s * 32 + lane);
        acc.x += v.x * n; acc.y += v.y * n; acc.z += v.z * n; acc.w += v.w * n;
    }
    float nd = __ldg(norm + warp);
    acc.x *= nd; acc.y *= nd; acc.z *= nd; acc.w *= nd;
    reinterpret_cast<uint2*>(out)[(size_t)warp * 32 + lane] = st_h4(acc);
}

// D=32: 8 lanes per node, lane covers 4 dims.
__global__ __launch_bounds__(256)
void prop_pull32(const __half* __restrict__ h, const float* __restrict__ norm,
                 const int* __restrict__ rowptr, const int* __restrict__ csr,
                 __half* __restrict__ out, int N) {
    int t = blockIdx.x * blockDim.x + threadIdx.x;
    int node = t >> 3;
    int lane = t & 7;
    if (node >= N) return;
    int beg = __ldg(rowptr + node), end = __ldg(rowptr + node + 1);
    const uint2* __restrict__ hv = reinterpret_cast<const uint2*>(h);
    float4 acc = make_float4(0.f, 0.f, 0.f, 0.f);
    int e = beg;
    for (; e + 4 <= end; e += 4) {
        int s0 = __ldg(csr + e), s1 = __ldg(csr + e + 1);
        int s2 = __ldg(csr + e + 2), s3 = __ldg(csr + e + 3);
        float n0 = __ldg(norm + s0), n1 = __ldg(norm + s1);
        float n2 = __ldg(norm + s2), n3 = __ldg(norm + s3);
        float4 v0 = ld_h4(hv + (size_t)s0 * 8 + lane);
        float4 v1 = ld_h4(hv + (size_t)s1 * 8 + lane);
        float4 v2 = ld_h4(hv + (size_t)s2 * 8 + lane);
        float4 v3 = ld_h4(hv + (size_t)s3 * 8 + lane);
        acc.x += v0.x * n0 + v1.x * n1 + v2.x * n2 + v3.x * n3;
        acc.y += v0.y * n0 + v1.y * n1 + v2.y * n2 + v3.y * n3;
        acc.z += v0.z * n0 + v1.z * n1 + v2.z * n2 + v3.z * n3;
        acc.w += v0.w * n0 + v1.w * n1 + v2.w * n2 + v3.w * n3;
    }
    for (; e < end; ++e) {
        int s = __ldg(csr + e);
        float n = __ldg(norm + s);
        float4 v = ld_h4(hv + (size_t)s * 8 + lane);
        acc.x += v.x * n; acc.y += v.y * n; acc.z += v.z * n; acc.w += v.w * n;
    }
    float nd = __ldg(norm + node);
    acc.x *= nd; acc.y *= nd; acc.z *= nd; acc.w *= nd;
    reinterpret_cast<uint2*>(out)[(size_t)node * 8 + lane] = st_h4(acc);
}

// ---------------------------------------------------------------------------
// TF32 tensor-core fused GEMM (R4 schedule; fp16 A inputs, fp32 W):
// out = relu(H0@W[0:DIN] + H1@W[DIN:2DIN] + H2@W[2DIN:3DIN] + b)
// ---------------------------------------------------------------------------
__device__ __forceinline__ uint32_t f2tf32(float f) {
    uint32_t u;
    asm("cvt.rna.tf32.f32 %0, %1;" : "=r"(u) : "f"(f));
    return u;
}

__device__ __forceinline__ void mma_tf32(float c[4], const uint32_t a[4], const uint32_t b[2]) {
    asm volatile(
        "mma.sync.aligned.m16n8k8.row.col.f32.tf32.tf32.f32 "
        "{%0,%1,%2,%3}, {%4,%5,%6,%7}, {%8,%9}, {%0,%1,%2,%3};"
        : "+f"(c[0]), "+f"(c[1]), "+f"(c[2]), "+f"(c[3])
        : "r"(a[0]), "r"(a[1]), "r"(a[2]), "r"(a[3]), "r"(b[0]), "r"(b[1]));
}

template <int DIN, bool HALF_OUT>
__global__ __launch_bounds__(256)
void gemm3_tf32(const __half* __restrict__ H0, const __half* __restrict__ H1,
                const __half* __restrict__ H2, const float* __restrict__ W,
                const float* __restrict__ bias, void* __restrict__ outv, int N) {
    __shared__ __align__(16) uint32_t As[32][132];   // As[k][m] (tf32 bits)
    __shared__ __align__(16) uint32_t Bs[32][128];   // Bs[k][n] (tf32 bits)

    const int tid     = threadIdx.x;
    const int wid     = tid >> 5;
    const int lane    = tid & 31;
    const int warp_m  = wid & 3;
    const int warp_n  = wid >> 2;
    const int groupID = lane >> 2;
    const int tig     = lane & 3;
    const int m0      = blockIdx.x * 128;

    float c[2][8][4];
#pragma unroll
    for (int mt = 0; mt < 2; mt++)
#pragma unroll
        for (int nt = 0; nt < 8; nt++)
#pragma unroll
            for (int i = 0; i < 4; i++) c[mt][nt][i] = 0.0f;

    const __half* srcs[3] = {H0, H1, H2};

    const int aRow = tid >> 3;          // 0..31
    const int aCol = (tid & 7) * 4;     // 0..28 (in halfs)
    const int bRow = tid >> 5;          // 0..7
    const int bCol = (tid & 31) * 4;    // 0..124

    for (int part = 0; part < 3; ++part) {
        const __half* __restrict__ Hp = srcs[part];
        for (int k0 = 0; k0 < DIN; k0 += 32) {
            // A tile: 128 rows x 32 k (fp16 -> tf32), stored transposed
#pragma unroll
            for (int r = 0; r < 4; ++r) {
                int row = m0 + r * 32 + aRow;
                float4 v = make_float4(0.f, 0.f, 0.f, 0.f);
                if (row < N) {
                    uint2 u = __ldg(reinterpret_cast<const uint2*>(
                        Hp + (size_t)row * DIN + k0 + aCol));
                    __half2 a = *reinterpret_cast<__half2*>(&u.x);
                    __half2 b = *reinterpret_cast<__half2*>(&u.y);
                    float2 fa = __half22float2(a);
                    float2 fb = __half22float2(b);
                    v = make_float4(fa.x, fa.y, fb.x, fb.y);
                }
                As[aCol + 0][r * 32 + aRow] = f2tf32(v.x);
                As[aCol + 1][r * 32 + aRow] = f2tf32(v.y);
                As[aCol + 2][r * 32 + aRow] = f2tf32(v.z);
                As[aCol + 3][r * 32 + aRow] = f2tf32(v.w);
            }
            // B tile: 32 k-rows x 128 n (fp32 weights)
#pragma unroll
            for (int r = 0; r < 4; ++r) {
                int krow = r * 8 + bRow;
                float4 v = __ldg(reinterpret_cast<const float4*>(
                    W + (size_t)(part * DIN + k0 + krow) * 128 + bCol));
                uint4 u;
                u.x = f2tf32(v.x); u.y = f2tf32(v.y);
                u.z = f2tf32(v.z); u.w = f2tf32(v.w);
                *reinterpret_cast<uint4*>(&Bs[krow][bCol]) = u;
            }
            __syncthreads();

#pragma unroll
            for (int kk = 0; kk < 4; ++kk) {
                const int kb = kk * 8;
                uint32_t a[2][4];
#pragma unroll
                for (int mt = 0; mt < 2; mt++) {
                    int m = warp_m * 32 + mt * 16 + groupID;
                    a[mt][0] = As[kb + tig][m];
                    a[mt][1] = As[kb + tig][m + 8];
                    a[mt][2] = As[kb + tig + 4][m];
                    a[mt][3] = As[kb + tig + 4][m + 8];
                }
                uint32_t b[8][2];
#pragma unroll
                for (int nt = 0; nt < 8; nt++) {
                    int n = warp_n * 64 + nt * 8 + groupID;
                    b[nt][0] = Bs[kb + tig][n];
                    b[nt][1] = Bs[kb + tig + 4][n];
                }
#pragma unroll
                for (int mt = 0; mt < 2; mt++)
#pragma unroll
                    for (int nt = 0; nt < 8; nt++)
                        mma_tf32(c[mt][nt], a[mt], b[nt]);
            }
            __syncthreads();
        }
    }

    // epilogue: bias + relu
#pragma unroll
    for (int nt = 0; nt < 8; nt++) {
        int col = warp_n * 64 + nt * 8 + tig * 2;
        float2 bv = __ldg(reinterpret_cast<const float2*>(bias + col));
#pragma unroll
        for (int mt = 0; mt < 2; mt++) {
            int row0 = m0 + warp_m * 32 + mt * 16 + groupID;
            int row1 = row0 + 8;
            float2 o0, o1;
            o0.x = fmaxf(c[mt][nt][0] + bv.x, 0.f);
            o0.y = fmaxf(c[mt][nt][1] + bv.y, 0.f);
            o1.x = fmaxf(c[mt][nt][2] + bv.x, 0.f);
            o1.y = fmaxf(c[mt][nt][3] + bv.y, 0.f);
            if (HALF_OUT) {
                __half* out = reinterpret_cast<__half*>(outv);
                if (row0 < N) {
                    __half2 hh = __floats2half2_rn(o0.x, o0.y);
                    *reinterpret_cast<__half2*>(out + (size_t)row0 * 128 + col) = hh;
                }
                if (row1 < N) {
                    __half2 hh = __floats2half2_rn(o1.x, o1.y);
                    *reinterpret_cast<__half2*>(out + (size_t)row1 * 128 + col) = hh;
                }
            } else {
                float* out = reinterpret_cast<float*>(outv);
                if (row0 < N)
                    *reinterpret_cast<float2*>(out + (size_t)row0 * 128 + col) = o0;
                if (row1 < N)
                    *reinterpret_cast<float2*>(out + (size_t)row1 * 128 + col) = o1;
            }
        }
    }
}

// ---------------------------------------------------------------------------
// launch
// ---------------------------------------------------------------------------
extern "C" void kernel_launch(void* const* d_in, const int* in_sizes, int n_in,
                              void* d_out, int out_size) {
    const float* x   = (const float*)d_in[0];
    const int*   src = (const int*)d_in[1];
    const int*   dst = (const int*)d_in[2];
    const float* W1  = (const float*)d_in[3];
    const float* b1  = (const float*)d_in[4];
    const float* W2  = (const float*)d_in[5];
    const float* b2  = (const float*)d_in[6];
    const float* W3  = (const float*)d_in[7];
    const float* b3  = (const float*)d_in[8];
    float* out = (float*)d_out;

    const int N = in_sizes[0] / 32;
    const int E = in_sizes[1];

    float *p_norm;
    __half *p_xh, *p_t1, *p_t2, *p_h1, *p_h2;
    int *p_cnt, *p_rowptr, *p_cursor, *p_bsums, *p_csr;
    cudaGetSymbolAddress((void**)&p_norm,   g_norm);
    cudaGetSymbolAddress((void**)&p_xh,     g_xh);
    cudaGetSymbolAddress((void**)&p_cnt,    g_cnt);
    cudaGetSymbolAddress((void**)&p_rowptr, g_rowptr);
    cudaGetSymbolAddress((void**)&p_cursor, g_cursor);
    cudaGetSymbolAddress((void**)&p_bsums,  g_bsums);
    cudaGetSymbolAddress((void**)&p_csr,    g_csr);
    cudaGetSymbolAddress((void**)&p_t1,     g_t1);
    cudaGetSymbolAddress((void**)&p_t2,     g_t2);
    cudaGetSymbolAddress((void**)&p_h1,     g_h1);
    cudaGetSymbolAddress((void**)&p_h2,     g_h2);

    const int TB = 256;
    const int nb = (N + 1023) / 1024;

    // x -> fp16
    const int n4 = (N * 32) / 4;
    f2h_kernel<<<(n4 + TB - 1) / TB, TB>>>(x, p_xh, n4);

    // degree + norm + CSR build (cnt re-zeroed by add_off each replay)
    hist_kernel<<<(E + TB - 1) / TB, TB>>>(dst, E, p_cnt);
    scan_block<<<nb, 256>>>(p_cnt, p_rowptr, p_bsums, p_norm, N);
    add_off<<<nb, 256>>>(p_rowptr, p_cursor, p_cnt, p_bsums, N, E, nb);
    scatter_kernel<<<(E + TB - 1) / TB, TB>>>(src, dst, E, p_cursor, p_csr);

    const int g128 = (N * 32 + TB - 1) / TB;   // warp per node
    const int g32  = (N * 8 + TB - 1) / TB;    // 8 lanes per node
    const int gg   = (N + 127) / 128;

    // ---- layer 1 (din = 32) ----
    prop_pull32<<<g32, TB>>>(p_xh, p_norm, p_rowptr, p_csr, p_t1, N);
    prop_pull32<<<g32, TB>>>(p_t1, p_norm, p_rowptr, p_csr, p_t2, N);
    gemm3_tf32<32, true><<<gg, 256>>>(p_xh, p_t1, p_t2, W1, b1, p_h1, N);

    // ---- layer 2 (din = 128) ----
    prop_pull128<<<g128, TB>>>(p_h1, p_norm, p_rowptr, p_csr, p_t1, N);
    prop_pull128<<<g128, TB>>>(p_t1, p_norm, p_rowptr, p_csr, p_t2, N);
    gemm3_tf32<128, true><<<gg, 256>>>(p_h1, p_t1, p_t2, W2, b2, p_h2, N);

    // ---- layer 3 (din = 128) ----
    prop_pull128<<<g128, TB>>>(p_h2, p_norm, p_rowptr, p_csr, p_t1, N);
    prop_pull128<<<g128, TB>>>(p_t1, p_norm, p_rowptr, p_csr, p_t2, N);
    gemm3_tf32<128, false><<<gg, 256>>>(p_h2, p_t1, p_t2, W3, b3, out, N);
}

// round 10
// speedup vs baseline: 1.5726x; 1.3144x over previous
#include <cuda_runtime.h>
#include <cuda_fp16.h>
#include <cstdint>

#define NMAX 100000
#define EMAX 1600000
#define HID  128

// Scratch (static device globals — allocation-free per harness rules).
// g_cnt zero-init at load; add_off re-zeros each run (graph-replay safe).
__device__ float  g_norm[NMAX];
__device__ int    g_cnt[NMAX];
__device__ int    g_rowptr[NMAX + 1];
__device__ int    g_cursor[NMAX];
__device__ int    g_bsums[128];
__device__ int    g_csr[EMAX];
__device__ __half g_xh[(size_t)NMAX * 32];
__device__ __half g_t1[(size_t)NMAX * HID];
__device__ __half g_t2[(size_t)NMAX * HID];
__device__ __half g_h1[(size_t)NMAX * HID];
__device__ __half g_h2[(size_t)NMAX * HID];

// ---------------------------------------------------------------------------
// x (fp32) -> xh (fp16)
// ---------------------------------------------------------------------------
__global__ void f2h_kernel(const float* __restrict__ x, __half* __restrict__ xh, int n4) {
    int i = blockIdx.x * blockDim.x + threadIdx.x;
    if (i < n4) {
        float4 v = __ldg(reinterpret_cast<const float4*>(x) + i);
        __half2 a = __floats2half2_rn(v.x, v.y);
        __half2 b = __floats2half2_rn(v.z, v.w);
        uint2 u;
        u.x = *reinterpret_cast<uint32_t*>(&a);
        u.y = *reinterpret_cast<uint32_t*>(&b);
        reinterpret_cast<uint2*>(xh)[i] = u;
    }
}

// ---------------------------------------------------------------------------
// degree histogram
// ---------------------------------------------------------------------------
__global__ void hist_kernel(const int* __restrict__ dst, int E, int* __restrict__ cnt) {
    int i = blockIdx.x * blockDim.x + threadIdx.x;
    if (i < E) atomicAdd(&cnt[dst[i]], 1);
}

// ---------------------------------------------------------------------------
// exclusive scan of cnt -> rowptr (1024 elems/block); also computes norm
// ---------------------------------------------------------------------------
__global__ void scan_block(const int* __restrict__ cnt, int* __restrict__ out,
                           int* __restrict__ bsums, float* __restrict__ norm, int N) {
    __shared__ int ss[256];
    const int tid  = threadIdx.x;
    const int base = blockIdx.x * 1024 + tid * 4;
    int local[4];
#pragma unroll
    for (int i = 0; i < 4; i++) {
        int g = base + i;
        local[i] = (g < N) ? cnt[g] : 0;
        if (g < N) norm[g] = rsqrtf(fmaxf((float)local[i], 1.0f));
    }
    int tsum = local[0] + local[1] + local[2] + local[3];
    ss[tid] = tsum;
    __syncthreads();
#pragma unroll
    for (int off = 1; off < 256; off <<= 1) {
        int v = (tid >= off) ? ss[tid - off] : 0;
        __syncthreads();
        ss[tid] += v;
        __syncthreads();
    }
    int run = ss[tid] - tsum;   // exclusive
#pragma unroll
    for (int i = 0; i < 4; i++) {
        int g = base + i;
        if (g < N) out[g] = run;
        run += local[i];
    }
    if (tid == 255) bsums[blockIdx.x] = ss[255];
}

// add block offsets (bsums prefix computed in-block), init cursor, re-zero cnt.
__global__ void add_off(int* __restrict__ rowptr, int* __restrict__ cursor,
                        int* __restrict__ cnt, const int* __restrict__ bsums,
                        int N, int E, int nb) {
    __shared__ int ss[256];
    const int tid = threadIdx.x;
    int v = (tid < nb && tid < blockIdx.x) ? bsums[tid] : 0;
    ss[tid] = v;
    __syncthreads();
#pragma unroll
    for (int off = 128; off > 0; off >>= 1) {
        if (tid < off) ss[tid] += ss[tid + off];
        __syncthreads();
    }
    const int o = ss[0];
    int g = blockIdx.x * 1024 + tid * 4;
#pragma unroll
    for (int i = 0; i < 4; i++) {
        if (g + i < N) {
            int val = rowptr[g + i] + o;
            rowptr[g + i] = val;
            cursor[g + i] = val;
            cnt[g + i]    = 0;
        }
    }
    if (blockIdx.x == 0 && tid == 0) rowptr[N] = E;
}

__global__ void scatter_kernel(const int* __restrict__ src, const int* __restrict__ dst,
                               int E, int* __restrict__ cursor, int* __restrict__ csr) {
    int e = blockIdx.x * blockDim.x + threadIdx.x;
    if (e < E) {
        int d = dst[e];
        int pos = atomicAdd(&cursor[d], 1);
        csr[pos] = src[e];
    }
}

// ---------------------------------------------------------------------------
// fp16 gather helpers
// ---------------------------------------------------------------------------
__device__ __forceinline__ float4 ld_h4(const uint2* p) {
    uint2 u = __ldg(p);
    __half2 a = *reinterpret_cast<__half2*>(&u.x);
    __half2 b = *reinterpret_cast<__half2*>(&u.y);
    float2 fa = __half22float2(a);
    float2 fb = __half22float2(b);
    return make_float4(fa.x, fa.y, fb.x, fb.y);
}

__device__ __forceinline__ uint2 st_h4(float4 v) {
    __half2 a = __floats2half2_rn(v.x, v.y);
    __half2 b = __floats2half2_rn(v.z, v.w);
    uint2 u;
    u.x = *reinterpret_cast<uint32_t*>(&a);
    u.y = *reinterpret_cast<uint32_t*>(&b);
    return u;
}

// ---------------------------------------------------------------------------
// pull propagation (R4 loop structure, fp16 rows, fp32 accumulate):
// out[d] = norm[d] * sum_{s in row(d)} norm[s]*h[s]
// ---------------------------------------------------------------------------
__global__ __launch_bounds__(256)
void prop_pull128(const __half* __restrict__ h, const float* __restrict__ norm,
                  const int* __restrict__ rowptr, const int* __restrict__ csr,
                  __half* __restrict__ out, int N) {
    int warp = (blockIdx.x * blockDim.x + threadIdx.x) >> 5;
    int lane = threadIdx.x & 31;
    if (warp >= N) return;
    int beg = __ldg(rowptr + warp), end = __ldg(rowptr + warp + 1);
    const uint2* __restrict__ hv = reinterpret_cast<const uint2*>(h);   // 4 halfs each
    float4 acc = make_float4(0.f, 0.f, 0.f, 0.f);
    int e = beg;
    for (; e + 4 <= end; e += 4) {
        int s0 = __ldg(csr + e), s1 = __ldg(csr + e + 1);
        int s2 = __ldg(csr + e + 2), s3 = __ldg(csr + e + 3);
        float n0 = __ldg(norm + s0), n1 = __ldg(norm + s1);
        float n2 = __ldg(norm + s2), n3 = __ldg(norm + s3);
        float4 v0 = ld_h4(hv + (size_t)s0 * 32 + lane);
        float4 v1 = ld_h4(hv + (size_t)s1 * 32 + lane);
        float4 v2 = ld_h4(hv + (size_t)s2 * 32 + lane);
        float4 v3 = ld_h4(hv + (size_t)s3 * 32 + lane);
        acc.x += v0.x * n0 + v1.x * n1 + v2.x * n2 + v3.x * n3;
        acc.y += v0.y * n0 + v1.y * n1 + v2.y * n2 + v3.y * n3;
        acc.z += v0.z * n0 + v1.z * n1 + v2.z * n2 + v3.z * n3;
        acc.w += v0.w * n0 + v1.w * n1 + v2.w * n2 + v3.w * n3;
    }
    for (; e < end; ++e) {
        int s = __ldg(csr + e);
        float n = __ldg(norm + s);
        float4 v = ld_h4(hv + (size_t)s * 32 + lane);
        acc.x += v.x * n; acc.y += v.y * n; acc.z += v.z * n; acc.w += v.w * n;
    }
    float nd = __ldg(norm + warp);
    acc.x *= nd; acc.y *= nd; acc.z *= nd; acc.w *= nd;
    reinterpret_cast<uint2*>(out)[(size_t)warp * 32 + lane] = st_h4(acc);
}

__global__ __launch_bounds__(256)
void prop_pull32(const __half* __restrict__ h, const float* __restrict__ norm,
                 const int* __restrict__ rowptr, const int* __restrict__ csr,
                 __half* __restrict__ out, int N) {
    int t = blockIdx.x * blockDim.x + threadIdx.x;
    int node = t >> 3;
    int lane = t & 7;
    if (node >= N) return;
    int beg = __ldg(rowptr + node), end = __ldg(rowptr + node + 1);
    const uint2* __restrict__ hv = reinterpret_cast<const uint2*>(h);
    float4 acc = make_float4(0.f, 0.f, 0.f, 0.f);
    int e = beg;
    for (; e + 4 <= end; e += 4) {
        int s0 = __ldg(csr + e), s1 = __ldg(csr + e + 1);
        int s2 = __ldg(csr + e + 2), s3 = __ldg(csr + e + 3);
        float n0 = __ldg(norm + s0), n1 = __ldg(norm + s1);
        float n2 = __ldg(norm + s2), n3 = __ldg(norm + s3);
        float4 v0 = ld_h4(hv + (size_t)s0 * 8 + lane);
        float4 v1 = ld_h4(hv + (size_t)s1 * 8 + lane);
        float4 v2 = ld_h4(hv + (size_t)s2 * 8 + lane);
        float4 v3 = ld_h4(hv + (size_t)s3 * 8 + lane);
        acc.x += v0.x * n0 + v1.x * n1 + v2.x * n2 + v3.x * n3;
        acc.y += v0.y * n0 + v1.y * n1 + v2.y * n2 + v3.y * n3;
        acc.z += v0.z * n0 + v1.z * n1 + v2.z * n2 + v3.z * n3;
        acc.w += v0.w * n0 + v1.w * n1 + v2.w * n2 + v3.w * n3;
    }
    for (; e < end; ++e) {
        int s = __ldg(csr + e);
        float n = __ldg(norm + s);
        float4 v = ld_h4(hv + (size_t)s * 8 + lane);
        acc.x += v.x * n; acc.y += v.y * n; acc.z += v.z * n; acc.w += v.w * n;
    }
    float nd = __ldg(norm + node);
    acc.x *= nd; acc.y *= nd; acc.z *= nd; acc.w *= nd;
    reinterpret_cast<uint2*>(out)[(size_t)node * 8 + lane] = st_h4(acc);
}

// ---------------------------------------------------------------------------
// FP16 tensor-core fused GEMM (m16n8k16.f16, fp32 accum):
// out = relu(H0@W[0:DIN] + H1@W[DIN:2DIN] + H2@W[2DIN:3DIN] + b)
// As[k2][m] holds half2 (A[m][2k2], A[m][2k2+1]); Bs[k2][n] holds
// half2 (B[2k2][n], B[2k2+1][n]). BK=32 (16 k-pairs), 2 mma k-steps/tile.
// ---------------------------------------------------------------------------
__device__ __forceinline__ void mma_f16(float c[4], const uint32_t a[4], const uint32_t b[2]) {
    asm volatile(
        "mma.sync.aligned.m16n8k16.row.col.f32.f16.f16.f32 "
        "{%0,%1,%2,%3}, {%4,%5,%6,%7}, {%8,%9}, {%0,%1,%2,%3};"
        : "+f"(c[0]), "+f"(c[1]), "+f"(c[2]), "+f"(c[3])
        : "r"(a[0]), "r"(a[1]), "r"(a[2]), "r"(a[3]), "r"(b[0]), "r"(b[1]));
}

template <int DIN, bool HALF_OUT>
__global__ __launch_bounds__(256)
void gemm3_fp16(const __half* __restrict__ H0, const __half* __restrict__ H1,
                const __half* __restrict__ H2, const float* __restrict__ W,
                const float* __restrict__ bias, void* __restrict__ outv, int N) {
    __shared__ __align__(16) __half2 As[16][132];   // [k-pair][m]
    __shared__ __align__(16) __half2 Bs[16][128];   // [k-pair][n]

    const int tid     = threadIdx.x;
    const int wid     = tid >> 5;
    const int lane    = tid & 31;
    const int warp_m  = wid & 3;
    const int warp_n  = wid >> 2;
    const int groupID = lane >> 2;
    const int tig     = lane & 3;
    const int m0      = blockIdx.x * 128;

    float c[2][8][4];
#pragma unroll
    for (int mt = 0; mt < 2; mt++)
#pragma unroll
        for (int nt = 0; nt < 8; nt++)
#pragma unroll
            for (int i = 0; i < 4; i++) c[mt][nt][i] = 0.0f;

    const __half* srcs[3] = {H0, H1, H2};

    const int aRow = tid >> 3;          // 0..31
    const int aCol = (tid & 7) * 4;     // 0..28 (halfs), pair index aCol/2
    const int bRow = tid >> 5;          // 0..7 (k-pair slot within r-iter)
    const int bCol = (tid & 31) * 4;    // 0..124

    for (int part = 0; part < 3; ++part) {
        const __half* __restrict__ Hp = srcs[part];
        for (int k0 = 0; k0 < DIN; k0 += 32) {
            // A tile: 128 rows x 32 k fp16, no conversion, stored as k-pairs
#pragma unroll
            for (int r = 0; r < 4; ++r) {
                int row = m0 + r * 32 + aRow;
                uint2 u = make_uint2(0u, 0u);
                if (row < N)
                    u = __ldg(reinterpret_cast<const uint2*>(
                        Hp + (size_t)row * DIN + k0 + aCol));
                As[(aCol >> 1) + 0][r * 32 + aRow] = *reinterpret_cast<__half2*>(&u.x);
                As[(aCol >> 1) + 1][r * 32 + aRow] = *reinterpret_cast<__half2*>(&u.y);
            }
            // B tile: 16 k-pairs x 128 n (fp32 W rows packed to half2 pairs)
#pragma unroll
            for (int r = 0; r < 2; ++r) {
                int p = r * 8 + bRow;   // k-pair 0..15
                const float* w0p = W + (size_t)(part * DIN + k0 + 2 * p) * 128 + bCol;
                float4 w0 = __ldg(reinterpret_cast<const float4*>(w0p));
                float4 w1 = __ldg(reinterpret_cast<const float4*>(w0p + 128));
                Bs[p][bCol + 0] = __floats2half2_rn(w0.x, w1.x);
                Bs[p][bCol + 1] = __floats2half2_rn(w0.y, w1.y);
                Bs[p][bCol + 2] = __floats2half2_rn(w0.z, w1.z);
                Bs[p][bCol + 3] = __floats2half2_rn(w0.w, w1.w);
            }
            __syncthreads();

#pragma unroll
            for (int kk = 0; kk < 2; ++kk) {
                const int kb = kk * 8;   // k-pair base: 8 pairs = 16 k per step
                uint32_t a[2][4];
#pragma unroll
                for (int mt = 0; mt < 2; mt++) {
                    int m = warp_m * 32 + mt * 16 + groupID;
                    a[mt][0] = *reinterpret_cast<const uint32_t*>(&As[kb + tig][m]);
                    a[mt][1] = *reinterpret_cast<const uint32_t*>(&As[kb + tig][m + 8]);
                    a[mt][2] = *reinterpret_cast<const uint32_t*>(&As[kb + tig + 4][m]);
                    a[mt][3] = *reinterpret_cast<const uint32_t*>(&As[kb + tig + 4][m + 8]);
                }
                uint32_t b[8][2];
#pragma unroll
                for (int nt = 0; nt < 8; nt++) {
                    int n = warp_n * 64 + nt * 8 + groupID;
                    b[nt][0] = *reinterpret_cast<const uint32_t*>(&Bs[kb + tig][n]);
                    b[nt][1] = *reinterpret_cast<const uint32_t*>(&Bs[kb + tig + 4][n]);
                }
#pragma unroll
                for (int mt = 0; mt < 2; mt++)
#pragma unroll
                    for (int nt = 0; nt < 8; nt++)
                        mma_f16(c[mt][nt], a[mt], b[nt]);
            }
            __syncthreads();
        }
    }

    // epilogue: bias + relu
#pragma unroll
    for (int nt = 0; nt < 8; nt++) {
        int col = warp_n * 64 + nt * 8 + tig * 2;
        float2 bv = __ldg(reinterpret_cast<const float2*>(bias + col));
#pragma unroll
        for (int mt = 0; mt < 2; mt++) {
            int row0 = m0 + warp_m * 32 + mt * 16 + groupID;
            int row1 = row0 + 8;
            float2 o0, o1;
            o0.x = fmaxf(c[mt][nt][0] + bv.x, 0.f);
            o0.y = fmaxf(c[mt][nt][1] + bv.y, 0.f);
            o1.x = fmaxf(c[mt][nt][2] + bv.x, 0.f);
            o1.y = fmaxf(c[mt][nt][3] + bv.y, 0.f);
            if (HALF_OUT) {
                __half* out = reinterpret_cast<__half*>(outv);
                if (row0 < N) {
                    __half2 hh = __floats2half2_rn(o0.x, o0.y);
                    *reinterpret_cast<__half2*>(out + (size_t)row0 * 128 + col) = hh;
                }
                if (row1 < N) {
                    __half2 hh = __floats2half2_rn(o1.x, o1.y);
                    *reinterpret_cast<__half2*>(out + (size_t)row1 * 128 + col) = hh;
                }
            } else {
                float* out = reinterpret_cast<float*>(outv);
                if (row0 < N)
                    *reinterpret_cast<float2*>(out + (size_t)row0 * 128 + col) = o0;
                if (row1 < N)
                    *reinterpret_cast<float2*>(out + (size_t)row1 * 128 + col) = o1;
            }
        }
    }
}

// ---------------------------------------------------------------------------
// launch
// ---------------------------------------------------------------------------
extern "C" void kernel_launch(void* const* d_in, const int* in_sizes, int n_in,
                              void* d_out, int out_size) {
    const float* x   = (const float*)d_in[0];
    const int*   src = (const int*)d_in[1];
    const int*   dst = (const int*)d_in[2];
    const float* W1  = (const float*)d_in[3];
    const float* b1  = (const float*)d_in[4];
    const float* W2  = (const float*)d_in[5];
    const float* b2  = (const float*)d_in[6];
    const float* W3  = (const float*)d_in[7];
    const float* b3  = (const float*)d_in[8];
    float* out = (float*)d_out;

    const int N = in_sizes[0] / 32;
    const int E = in_sizes[1];

    float *p_norm;
    __half *p_xh, *p_t1, *p_t2, *p_h1, *p_h2;
    int *p_cnt, *p_rowptr, *p_cursor, *p_bsums, *p_csr;
    cudaGetSymbolAddress((void**)&p_norm,   g_norm);
    cudaGetSymbolAddress((void**)&p_xh,     g_xh);
    cudaGetSymbolAddress((void**)&p_cnt,    g_cnt);
    cudaGetSymbolAddress((void**)&p_rowptr, g_rowptr);
    cudaGetSymbolAddress((void**)&p_cursor, g_cursor);
    cudaGetSymbolAddress((void**)&p_bsums,  g_bsums);
    cudaGetSymbolAddress((void**)&p_csr,    g_csr);
    cudaGetSymbolAddress((void**)&p_t1,     g_t1);
    cudaGetSymbolAddress((void**)&p_t2,     g_t2);
    cudaGetSymbolAddress((void**)&p_h1,     g_h1);
    cudaGetSymbolAddress((void**)&p_h2,     g_h2);

    const int TB = 256;
    const int nb = (N + 1023) / 1024;

    // x -> fp16
    const int n4 = (N * 32) / 4;
    f2h_kernel<<<(n4 + TB - 1) / TB, TB>>>(x, p_xh, n4);

    // degree + norm + CSR build (cnt re-zeroed by add_off each replay)
    hist_kernel<<<(E + TB - 1) / TB, TB>>>(dst, E, p_cnt);
    scan_block<<<nb, 256>>>(p_cnt, p_rowptr, p_bsums, p_norm, N);
    add_off<<<nb, 256>>>(p_rowptr, p_cursor, p_cnt, p_bsums, N, E, nb);
    scatter_kernel<<<(E + TB - 1) / TB, TB>>>(src, dst, E, p_cursor, p_csr);

    const int g128 = (N * 32 + TB - 1) / TB;   // warp per node
    const int g32  = (N * 8 + TB - 1) / TB;    // 8 lanes per node
    const int gg   = (N + 127) / 128;

    // ---- layer 1 (din = 32) ----
    prop_pull32<<<g32, TB>>>(p_xh, p_norm, p_rowptr, p_csr, p_t1, N);
    prop_pull32<<<g32, TB>>>(p_t1, p_norm, p_rowptr, p_csr, p_t2, N);
    gemm3_fp16<32, true><<<gg, 256>>>(p_xh, p_t1, p_t2, W1, b1, p_h1, N);

    // ---- layer 2 (din = 128) ----
    prop_pull128<<<g128, TB>>>(p_h1, p_norm, p_rowptr, p_csr, p_t1, N);
    prop_pull128<<<g128, TB>>>(p_t1, p_norm, p_rowptr, p_csr, p_t2, N);
    gemm3_fp16<128, true><<<gg, 256>>>(p_h1, p_t1, p_t2, W2, b2, p_h2, N);

    // ---- layer 3 (din = 128) ----
    prop_pull128<<<g128, TB>>>(p_h2, p_norm, p_rowptr, p_csr, p_t1, N);
    prop_pull128<<<g128, TB>>>(p_t1, p_norm, p_rowptr, p_csr, p_t2, N);
    gemm3_fp16<128, false><<<gg, 256>>>(p_h2, p_t1, p_t2, W3, b3, out, N);
}

// round 11
// speedup vs baseline: 1.6502x; 1.0493x over previous
#include <cuda_runtime.h>
#include <cuda_fp16.h>
#include <cstdint>

#define NMAX 100000
#define EMAX 1600000
#define HID  128

// Scratch (static device globals — allocation-free per harness rules).
// g_cnt zero-init at load; add_off re-zeros each run (graph-replay safe).
__device__ float  g_norm[NMAX];     // deg^-1/2
__device__ float  g_scale2[NMAX];   // deg^-1  (= norm^2)
__device__ __half g_rnh[NMAX];      // deg^+1/2 (= 1/norm), fp16
__device__ int    g_cnt[NMAX];
__device__ int    g_rowptr[NMAX + 1];
__device__ int    g_cursor[NMAX];
__device__ int    g_bsums[128];
__device__ int    g_csr[EMAX];
__device__ __half g_xh[(size_t)NMAX * 32];   // u0 = norm ⊙ x
__device__ __half g_t1[(size_t)NMAX * HID];
__device__ __half g_t2[(size_t)NMAX * HID];
__device__ __half g_h1[(size_t)NMAX * HID];
__device__ __half g_h2[(size_t)NMAX * HID];

// ---------------------------------------------------------------------------
// degree histogram
// ---------------------------------------------------------------------------
__global__ void hist_kernel(const int* __restrict__ dst, int E, int* __restrict__ cnt) {
    int i = blockIdx.x * blockDim.x + threadIdx.x;
    if (i < E) atomicAdd(&cnt[dst[i]], 1);
}

// ---------------------------------------------------------------------------
// exclusive scan of cnt -> rowptr (1024 elems/block); also norm/scale2/rnh
// ---------------------------------------------------------------------------
__global__ void scan_block(const int* __restrict__ cnt, int* __restrict__ out,
                           int* __restrict__ bsums, float* __restrict__ norm,
                           float* __restrict__ scale2, __half* __restrict__ rnh, int N) {
    __shared__ int ss[256];
    const int tid  = threadIdx.x;
    const int base = blockIdx.x * 1024 + tid * 4;
    int local[4];
#pragma unroll
    for (int i = 0; i < 4; i++) {
        int g = base + i;
        local[i] = (g < N) ? cnt[g] : 0;
        if (g < N) {
            float d  = fmaxf((float)local[i], 1.0f);
            float nv = rsqrtf(d);
            norm[g]   = nv;
            scale2[g] = nv * nv;
            rnh[g]    = __float2half(sqrtf(d));
        }
    }
    int tsum = local[0] + local[1] + local[2] + local[3];
    ss[tid] = tsum;
    __syncthreads();
#pragma unroll
    for (int off = 1; off < 256; off <<= 1) {
        int v = (tid >= off) ? ss[tid - off] : 0;
        __syncthreads();
        ss[tid] += v;
        __syncthreads();
    }
    int run = ss[tid] - tsum;   // exclusive
#pragma unroll
    for (int i = 0; i < 4; i++) {
        int g = base + i;
        if (g < N) out[g] = run;
        run += local[i];
    }
    if (tid == 255) bsums[blockIdx.x] = ss[255];
}

// add block offsets (bsums prefix computed in-block), init cursor, re-zero cnt.
__global__ void add_off(int* __restrict__ rowptr, int* __restrict__ cursor,
                        int* __restrict__ cnt, const int* __restrict__ bsums,
                        int N, int E, int nb) {
    __shared__ int ss[256];
    const int tid = threadIdx.x;
    int v = (tid < nb && tid < blockIdx.x) ? bsums[tid] : 0;
    ss[tid] = v;
    __syncthreads();
#pragma unroll
    for (int off = 128; off > 0; off >>= 1) {
        if (tid < off) ss[tid] += ss[tid + off];
        __syncthreads();
    }
    const int o = ss[0];
    int g = blockIdx.x * 1024 + tid * 4;
#pragma unroll
    for (int i = 0; i < 4; i++) {
        if (g + i < N) {
            int val = rowptr[g + i] + o;
            rowptr[g + i] = val;
            cursor[g + i] = val;
            cnt[g + i]    = 0;
        }
    }
    if (blockIdx.x == 0 && tid == 0) rowptr[N] = E;
}

__global__ void scatter_kernel(const int* __restrict__ src, const int* __restrict__ dst,
                               int E, int* __restrict__ cursor, int* __restrict__ csr) {
    int e = blockIdx.x * blockDim.x + threadIdx.x;
    if (e < E) {
        int d = dst[e];
        int pos = atomicAdd(&cursor[d], 1);
        csr[pos] = src[e];
    }
}

// ---------------------------------------------------------------------------
// x (fp32) -> u0 = norm ⊙ x (fp16). Thread handles 4 floats; 8 float4s/row.
// ---------------------------------------------------------------------------
__global__ void f2h_scale(const float* __restrict__ x, const float* __restrict__ norm,
                          __half* __restrict__ u, int n4) {
    int i = blockIdx.x * blockDim.x + threadIdx.x;
    if (i < n4) {
        float nv = __ldg(norm + (i >> 3));
        float4 v = __ldg(reinterpret_cast<const float4*>(x) + i);
        __half2 a = __floats2half2_rn(v.x * nv, v.y * nv);
        __half2 b = __floats2half2_rn(v.z * nv, v.w * nv);
        uint2 o;
        o.x = *reinterpret_cast<uint32_t*>(&a);
        o.y = *reinterpret_cast<uint32_t*>(&b);
        reinterpret_cast<uint2*>(u)[i] = o;
    }
}

// ---------------------------------------------------------------------------
// fp16 helpers
// ---------------------------------------------------------------------------
__device__ __forceinline__ float4 ld_h4(const uint2* p) {
    uint2 u = __ldg(p);
    __half2 a = *reinterpret_cast<__half2*>(&u.x);
    __half2 b = *reinterpret_cast<__half2*>(&u.y);
    float2 fa = __half22float2(a);
    float2 fb = __half22float2(b);
    return make_float4(fa.x, fa.y, fb.x, fb.y);
}

__device__ __forceinline__ uint2 st_h4(float4 v) {
    __half2 a = __floats2half2_rn(v.x, v.y);
    __half2 b = __floats2half2_rn(v.z, v.w);
    uint2 u;
    u.x = *reinterpret_cast<uint32_t*>(&a);
    u.y = *reinterpret_cast<uint32_t*>(&b);
    return u;
}

// ---------------------------------------------------------------------------
// u-space pull propagation: u_out[d] = scale2[d] * sum_{s in row(d)} u[s]
// Pure gather-sum: NO per-edge norm load. R4/R10-proven unroll-4 structure.
// ---------------------------------------------------------------------------
__global__ __launch_bounds__(256)
void prop_pull128(const __half* __restrict__ u, const float* __restrict__ scale2,
                  const int* __restrict__ rowptr, const int* __restrict__ csr,
                  __half* __restrict__ out, int N) {
    int warp = (blockIdx.x * blockDim.x + threadIdx.x) >> 5;
    int lane = threadIdx.x & 31;
    if (warp >= N) return;
    int beg = __ldg(rowptr + warp), end = __ldg(rowptr + warp + 1);
    const uint2* __restrict__ hv = reinterpret_cast<const uint2*>(u);
    float4 acc = make_float4(0.f, 0.f, 0.f, 0.f);
    int e = beg;
    for (; e + 4 <= end; e += 4) {
        int s0 = __ldg(csr + e), s1 = __ldg(csr + e + 1);
        int s2 = __ldg(csr + e + 2), s3 = __ldg(csr + e + 3);
        float4 v0 = ld_h4(hv + (size_t)s0 * 32 + lane);
        float4 v1 = ld_h4(hv + (size_t)s1 * 32 + lane);
        float4 v2 = ld_h4(hv + (size_t)s2 * 32 + lane);
        float4 v3 = ld_h4(hv + (size_t)s3 * 32 + lane);
        acc.x += v0.x + v1.x + v2.x + v3.x;
        acc.y += v0.y + v1.y + v2.y + v3.y;
        acc.z += v0.z + v1.z + v2.z + v3.z;
        acc.w += v0.w + v1.w + v2.w + v3.w;
    }
    for (; e < end; ++e) {
        int s = __ldg(csr + e);
        float4 v = ld_h4(hv + (size_t)s * 32 + lane);
        acc.x += v.x; acc.y += v.y; acc.z += v.z; acc.w += v.w;
    }
    float s2v = __ldg(scale2 + warp);
    acc.x *= s2v; acc.y *= s2v; acc.z *= s2v; acc.w *= s2v;
    reinterpret_cast<uint2*>(out)[(size_t)warp * 32 + lane] = st_h4(acc);
}

__global__ __launch_bounds__(256)
void prop_pull32(const __half* __restrict__ u, const float* __restrict__ scale2,
                 const int* __restrict__ rowptr, const int* __restrict__ csr,
                 __half* __restrict__ out, int N) {
    int t = blockIdx.x * blockDim.x + threadIdx.x;
    int node = t >> 3;
    int lane = t & 7;
    if (node >= N) return;
    int beg = __ldg(rowptr + node), end = __ldg(rowptr + node + 1);
    const uint2* __restrict__ hv = reinterpret_cast<const uint2*>(u);
    float4 acc = make_float4(0.f, 0.f, 0.f, 0.f);
    int e = beg;
    for (; e + 4 <= end; e += 4) {
        int s0 = __ldg(csr + e), s1 = __ldg(csr + e + 1);
        int s2 = __ldg(csr + e + 2), s3 = __ldg(csr + e + 3);
        float4 v0 = ld_h4(hv + (size_t)s0 * 8 + lane);
        float4 v1 = ld_h4(hv + (size_t)s1 * 8 + lane);
        float4 v2 = ld_h4(hv + (size_t)s2 * 8 + lane);
        float4 v3 = ld_h4(hv + (size_t)s3 * 8 + lane);
        acc.x += v0.x + v1.x + v2.x + v3.x;
        acc.y += v0.y + v1.y + v2.y + v3.y;
        acc.z += v0.z + v1.z + v2.z + v3.z;
        acc.w += v0.w + v1.w + v2.w + v3.w;
    }
    for (; e < end; ++e) {
        int s = __ldg(csr + e);
        float4 v = ld_h4(hv + (size_t)s * 8 + lane);
        acc.x += v.x; acc.y += v.y; acc.z += v.z; acc.w += v.w;
    }
    float s2v = __ldg(scale2 + node);
    acc.x *= s2v; acc.y *= s2v; acc.z *= s2v; acc.w *= s2v;
    reinterpret_cast<uint2*>(out)[(size_t)node * 8 + lane] = st_h4(acc);
}

// ---------------------------------------------------------------------------
// FP16 tensor-core fused GEMM, u-space aware:
// A rows are u-space -> scaled by rnh[row] (= 1/norm) at load.
// true_out = relu(concat @ W + b); epilogue writes norm[row]*true_out (fp16)
// when HALF_OUT (feeds next u-space prop) or plain fp32 for the final layer.
// ---------------------------------------------------------------------------
__device__ __forceinline__ void mma_f16(float c[4], const uint32_t a[4], const uint32_t b[2]) {
    asm volatile(
        "mma.sync.aligned.m16n8k16.row.col.f32.f16.f16.f32 "
        "{%0,%1,%2,%3}, {%4,%5,%6,%7}, {%8,%9}, {%0,%1,%2,%3};"
        : "+f"(c[0]), "+f"(c[1]), "+f"(c[2]), "+f"(c[3])
        : "r"(a[0]), "r"(a[1]), "r"(a[2]), "r"(a[3]), "r"(b[0]), "r"(b[1]));
}

template <int DIN, bool HALF_OUT>
__global__ __launch_bounds__(256)
void gemm3_fp16(const __half* __restrict__ H0, const __half* __restrict__ H1,
                const __half* __restrict__ H2, const float* __restrict__ W,
                const float* __restrict__ bias, const __half* __restrict__ rnh,
                const float* __restrict__ normf, void* __restrict__ outv, int N) {
    __shared__ __align__(16) __half2 As[16][132];   // [k-pair][m]
    __shared__ __align__(16) __half2 Bs[16][128];   // [k-pair][n]

    const int tid     = threadIdx.x;
    const int wid     = tid >> 5;
    const int lane    = tid & 31;
    const int warp_m  = wid & 3;
    const int warp_n  = wid >> 2;
    const int groupID = lane >> 2;
    const int tig     = lane & 3;
    const int m0      = blockIdx.x * 128;

    float c[2][8][4];
#pragma unroll
    for (int mt = 0; mt < 2; mt++)
#pragma unroll
        for (int nt = 0; nt < 8; nt++)
#pragma unroll
            for (int i = 0; i < 4; i++) c[mt][nt][i] = 0.0f;

    const __half* srcs[3] = {H0, H1, H2};

    const int aRow = tid >> 3;          // 0..31
    const int aCol = (tid & 7) * 4;     // 0..28 halfs
    const int bRow = tid >> 5;          // 0..7
    const int bCol = (tid & 31) * 4;    // 0..124

    for (int part = 0; part < 3; ++part) {
        const __half* __restrict__ Hp = srcs[part];
        for (int k0 = 0; k0 < DIN; k0 += 32) {
            // A tile: fp16 u-space rows, scaled by rnh[row] (HMUL2, no cvt)
#pragma unroll
            for (int r = 0; r < 4; ++r) {
                int row = m0 + r * 32 + aRow;
                uint2 u = make_uint2(0u, 0u);
                __half2 rn2 = __floats2half2_rn(0.f, 0.f);
                if (row < N) {
                    u = __ldg(reinterpret_cast<const uint2*>(
                        Hp + (size_t)row * DIN + k0 + aCol));
                    rn2 = __half2half2(__ldg(rnh + row));
                }
                As[(aCol >> 1) + 0][r * 32 + aRow] =
                    __hmul2(*reinterpret_cast<__half2*>(&u.x), rn2);
                As[(aCol >> 1) + 1][r * 32 + aRow] =
                    __hmul2(*reinterpret_cast<__half2*>(&u.y), rn2);
            }
            // B tile: 16 k-pairs x 128 n (fp32 W packed to half2 k-pairs)
#pragma unroll
            for (int r = 0; r < 2; ++r) {
                int p = r * 8 + bRow;   // k-pair 0..15
                const float* w0p = W + (size_t)(part * DIN + k0 + 2 * p) * 128 + bCol;
                float4 w0 = __ldg(reinterpret_cast<const float4*>(w0p));
                float4 w1 = __ldg(reinterpret_cast<const float4*>(w0p + 128));
                Bs[p][bCol + 0] = __floats2half2_rn(w0.x, w1.x);
                Bs[p][bCol + 1] = __floats2half2_rn(w0.y, w1.y);
                Bs[p][bCol + 2] = __floats2half2_rn(w0.z, w1.z);
                Bs[p][bCol + 3] = __floats2half2_rn(w0.w, w1.w);
            }
            __syncthreads();

#pragma unroll
            for (int kk = 0; kk < 2; ++kk) {
                const int kb = kk * 8;
                uint32_t a[2][4];
#pragma unroll
                for (int mt = 0; mt < 2; mt++) {
                    int m = warp_m * 32 + mt * 16 + groupID;
                    a[mt][0] = *reinterpret_cast<const uint32_t*>(&As[kb + tig][m]);
                    a[mt][1] = *reinterpret_cast<const uint32_t*>(&As[kb + tig][m + 8]);
                    a[mt][2] = *reinterpret_cast<const uint32_t*>(&As[kb + tig + 4][m]);
                    a[mt][3] = *reinterpret_cast<const uint32_t*>(&As[kb + tig + 4][m + 8]);
                }
                uint32_t b[8][2];
#pragma unroll
                for (int nt = 0; nt < 8; nt++) {
                    int n = warp_n * 64 + nt * 8 + groupID;
                    b[nt][0] = *reinterpret_cast<const uint32_t*>(&Bs[kb + tig][n]);
                    b[nt][1] = *reinterpret_cast<const uint32_t*>(&Bs[kb + tig + 4][n]);
                }
#pragma unroll
                for (int mt = 0; mt < 2; mt++)
#pragma unroll
                    for (int nt = 0; nt < 8; nt++)
                        mma_f16(c[mt][nt], a[mt], b[nt]);
            }
            __syncthreads();
        }
    }

    // epilogue: bias + relu (+ norm scale when writing u-space fp16)
#pragma unroll
    for (int mt = 0; mt < 2; mt++) {
        int row0 = m0 + warp_m * 32 + mt * 16 + groupID;
        int row1 = row0 + 8;
        float nr0 = 1.f, nr1 = 1.f;
        if (HALF_OUT) {
            if (row0 < N) nr0 = __ldg(normf + row0);
            if (row1 < N) nr1 = __ldg(normf + row1);
        }
#pragma unroll
        for (int nt = 0; nt < 8; nt++) {
            int col = warp_n * 64 + nt * 8 + tig * 2;
            float2 bv = __ldg(reinterpret_cast<const float2*>(bias + col));
            float2 o0, o1;
            o0.x = fmaxf(c[mt][nt][0] + bv.x, 0.f);
            o0.y = fmaxf(c[mt][nt][1] + bv.y, 0.f);
            o1.x = fmaxf(c[mt][nt][2] + bv.x, 0.f);
            o1.y = fmaxf(c[mt][nt][3] + bv.y, 0.f);
            if (HALF_OUT) {
                __half* out = reinterpret_cast<__half*>(outv);
                if (row0 < N) {
                    __half2 hh = __floats2half2_rn(o0.x * nr0, o0.y * nr0);
                    *reinterpret_cast<__half2*>(out + (size_t)row0 * 128 + col) = hh;
                }
                if (row1 < N) {
                    __half2 hh = __floats2half2_rn(o1.x * nr1, o1.y * nr1);
                    *reinterpret_cast<__half2*>(out + (size_t)row1 * 128 + col) = hh;
                }
            } else {
                float* out = reinterpret_cast<float*>(outv);
                if (row0 < N)
                    *reinterpret_cast<float2*>(out + (size_t)row0 * 128 + col) = o0;
                if (row1 < N)
                    *reinterpret_cast<float2*>(out + (size_t)row1 * 128 + col) = o1;
            }
        }
    }
}

// ---------------------------------------------------------------------------
// launch
// ---------------------------------------------------------------------------
extern "C" void kernel_launch(void* const* d_in, const int* in_sizes, int n_in,
                              void* d_out, int out_size) {
    const float* x   = (const float*)d_in[0];
    const int*   src = (const int*)d_in[1];
    const int*   dst = (const int*)d_in[2];
    const float* W1  = (const float*)d_in[3];
    const float* b1  = (const float*)d_in[4];
    const float* W2  = (const float*)d_in[5];
    const float* b2  = (const float*)d_in[6];
    const float* W3  = (const float*)d_in[7];
    const float* b3  = (const float*)d_in[8];
    float* out = (float*)d_out;

    const int N = in_sizes[0] / 32;
    const int E = in_sizes[1];

    float *p_norm, *p_scale2;
    __half *p_rnh, *p_xh, *p_t1, *p_t2, *p_h1, *p_h2;
    int *p_cnt, *p_rowptr, *p_cursor, *p_bsums, *p_csr;
    cudaGetSymbolAddress((void**)&p_norm,   g_norm);
    cudaGetSymbolAddress((void**)&p_scale2, g_scale2);
    cudaGetSymbolAddress((void**)&p_rnh,    g_rnh);
    cudaGetSymbolAddress((void**)&p_xh,     g_xh);
    cudaGetSymbolAddress((void**)&p_cnt,    g_cnt);
    cudaGetSymbolAddress((void**)&p_rowptr, g_rowptr);
    cudaGetSymbolAddress((void**)&p_cursor, g_cursor);
    cudaGetSymbolAddress((void**)&p_bsums,  g_bsums);
    cudaGetSymbolAddress((void**)&p_csr,    g_csr);
    cudaGetSymbolAddress((void**)&p_t1,     g_t1);
    cudaGetSymbolAddress((void**)&p_t2,     g_t2);
    cudaGetSymbolAddress((void**)&p_h1,     g_h1);
    cudaGetSymbolAddress((void**)&p_h2,     g_h2);

    const int TB = 256;
    const int nb = (N + 1023) / 1024;

    // degree + norm/scale2/rnh + CSR build (cnt re-zeroed by add_off)
    hist_kernel<<<(E + TB - 1) / TB, TB>>>(dst, E, p_cnt);
    scan_block<<<nb, 256>>>(p_cnt, p_rowptr, p_bsums, p_norm, p_scale2, p_rnh, N);
    add_off<<<nb, 256>>>(p_rowptr, p_cursor, p_cnt, p_bsums, N, E, nb);
    scatter_kernel<<<(E + TB - 1) / TB, TB>>>(src, dst, E, p_cursor, p_csr);

    // u0 = norm ⊙ x (fp16); needs norm from scan_block
    const int n4 = (N * 32) / 4;
    f2h_scale<<<(n4 + TB - 1) / TB, TB>>>(x, p_norm, p_xh, n4);

    const int g128 = (N * 32 + TB - 1) / TB;   // warp per node
    const int g32  = (N * 8 + TB - 1) / TB;    // 8 lanes per node
    const int gg   = (N + 127) / 128;

    // ---- layer 1 (din = 32) ----
    prop_pull32<<<g32, TB>>>(p_xh, p_scale2, p_rowptr, p_csr, p_t1, N);
    prop_pull32<<<g32, TB>>>(p_t1, p_scale2, p_rowptr, p_csr, p_t2, N);
    gemm3_fp16<32, true><<<gg, 256>>>(p_xh, p_t1, p_t2, W1, b1, p_rnh, p_norm, p_h1, N);

    // ---- layer 2 (din = 128) ----
    prop_pull128<<<g128, TB>>>(p_h1, p_scale2, p_rowptr, p_csr, p_t1, N);
    prop_pull128<<<g128, TB>>>(p_t1, p_scale2, p_rowptr, p_csr, p_t2, N);
    gemm3_fp16<128, true><<<gg, 256>>>(p_h1, p_t1, p_t2, W2, b2, p_rnh, p_norm, p_h2, N);

    // ---- layer 3 (din = 128) ----
    prop_pull128<<<g128, TB>>>(p_h2, p_scale2, p_rowptr, p_csr, p_t1, N);
    prop_pull128<<<g128, TB>>>(p_t1, p_scale2, p_rowptr, p_csr, p_t2, N);
    gemm3_fp16<128, false><<<gg, 256>>>(p_h2, p_t1, p_t2, W3, b3, p_rnh, p_norm, out, N);
}

// round 12
// speedup vs baseline: 1.7278x; 1.0470x over previous
#include <cuda_runtime.h>
#include <cuda_fp16.h>
#include <cstdint>

#define NMAX 100000
#define EMAX 1600000
#define HID  128

// Scratch (static device globals — allocation-free per harness rules).
// g_cnt zero-init at load; add_off re-zeros each run (graph-replay safe).
__device__ float  g_norm[NMAX];     // deg^-1/2
__device__ float  g_scale2[NMAX];   // deg^-1  (= norm^2)
__device__ __half g_rnh[NMAX];      // deg^+1/2 (= 1/norm), fp16
__device__ int    g_cnt[NMAX];
__device__ int    g_rowptr[NMAX + 1];
__device__ int    g_cursor[NMAX];
__device__ int    g_bsums[128];
__device__ int    g_csr[EMAX];
__device__ __half g_xh[(size_t)NMAX * 32];   // u0 = norm ⊙ x
__device__ __half g_t1[(size_t)NMAX * HID];
__device__ __half g_t2[(size_t)NMAX * HID];
__device__ __half g_h1[(size_t)NMAX * HID];
__device__ __half g_h2[(size_t)NMAX * HID];

// ---------------------------------------------------------------------------
// degree histogram
// ---------------------------------------------------------------------------
__global__ void hist_kernel(const int* __restrict__ dst, int E, int* __restrict__ cnt) {
    int i = blockIdx.x * blockDim.x + threadIdx.x;
    if (i < E) atomicAdd(&cnt[dst[i]], 1);
}

// ---------------------------------------------------------------------------
// exclusive scan of cnt -> rowptr (1024 elems/block); also norm/scale2/rnh
// ---------------------------------------------------------------------------
__global__ void scan_block(const int* __restrict__ cnt, int* __restrict__ out,
                           int* __restrict__ bsums, float* __restrict__ norm,
                           float* __restrict__ scale2, __half* __restrict__ rnh, int N) {
    __shared__ int ss[256];
    const int tid  = threadIdx.x;
    const int base = blockIdx.x * 1024 + tid * 4;
    int local[4];
#pragma unroll
    for (int i = 0; i < 4; i++) {
        int g = base + i;
        local[i] = (g < N) ? cnt[g] : 0;
        if (g < N) {
            float d  = fmaxf((float)local[i], 1.0f);
            float nv = rsqrtf(d);
            norm[g]   = nv;
            scale2[g] = nv * nv;
            rnh[g]    = __float2half(sqrtf(d));
        }
    }
    int tsum = local[0] + local[1] + local[2] + local[3];
    ss[tid] = tsum;
    __syncthreads();
#pragma unroll
    for (int off = 1; off < 256; off <<= 1) {
        int v = (tid >= off) ? ss[tid - off] : 0;
        __syncthreads();
        ss[tid] += v;
        __syncthreads();
    }
    int run = ss[tid] - tsum;   // exclusive
#pragma unroll
    for (int i = 0; i < 4; i++) {
        int g = base + i;
        if (g < N) out[g] = run;
        run += local[i];
    }
    if (tid == 255) bsums[blockIdx.x] = ss[255];
}

// add block offsets (bsums prefix computed in-block), init cursor, re-zero cnt.
__global__ void add_off(int* __restrict__ rowptr, int* __restrict__ cursor,
                        int* __restrict__ cnt, const int* __restrict__ bsums,
                        int N, int E, int nb) {
    __shared__ int ss[256];
    const int tid = threadIdx.x;
    int v = (tid < nb && tid < blockIdx.x) ? bsums[tid] : 0;
    ss[tid] = v;
    __syncthreads();
#pragma unroll
    for (int off = 128; off > 0; off >>= 1) {
        if (tid < off) ss[tid] += ss[tid + off];
        __syncthreads();
    }
    const int o = ss[0];
    int g = blockIdx.x * 1024 + tid * 4;
#pragma unroll
    for (int i = 0; i < 4; i++) {
        if (g + i < N) {
            int val = rowptr[g + i] + o;
            rowptr[g + i] = val;
            cursor[g + i] = val;
            cnt[g + i]    = 0;
        }
    }
    if (blockIdx.x == 0 && tid == 0) rowptr[N] = E;
}

__global__ void scatter_kernel(const int* __restrict__ src, const int* __restrict__ dst,
                               int E, int* __restrict__ cursor, int* __restrict__ csr) {
    int e = blockIdx.x * blockDim.x + threadIdx.x;
    if (e < E) {
        int d = dst[e];
        int pos = atomicAdd(&cursor[d], 1);
        csr[pos] = src[e];
    }
}

// ---------------------------------------------------------------------------
// x (fp32) -> u0 = norm ⊙ x (fp16). Thread handles 4 floats; 8 float4s/row.
// ---------------------------------------------------------------------------
__global__ void f2h_scale(const float* __restrict__ x, const float* __restrict__ norm,
                          __half* __restrict__ u, int n4) {
    int i = blockIdx.x * blockDim.x + threadIdx.x;
    if (i < n4) {
        float nv = __ldg(norm + (i >> 3));
        float4 v = __ldg(reinterpret_cast<const float4*>(x) + i);
        __half2 a = __floats2half2_rn(v.x * nv, v.y * nv);
        __half2 b = __floats2half2_rn(v.z * nv, v.w * nv);
        uint2 o;
        o.x = *reinterpret_cast<uint32_t*>(&a);
        o.y = *reinterpret_cast<uint32_t*>(&b);
        reinterpret_cast<uint2*>(u)[i] = o;
    }
}

// ---------------------------------------------------------------------------
// fp16 helpers
// ---------------------------------------------------------------------------
__device__ __forceinline__ float4 ld_h4(const uint2* p) {
    uint2 u = __ldg(p);
    __half2 a = *reinterpret_cast<__half2*>(&u.x);
    __half2 b = *reinterpret_cast<__half2*>(&u.y);
    float2 fa = __half22float2(a);
    float2 fb = __half22float2(b);
    return make_float4(fa.x, fa.y, fb.x, fb.y);
}

__device__ __forceinline__ uint2 st_h4(float4 v) {
    __half2 a = __floats2half2_rn(v.x, v.y);
    __half2 b = __floats2half2_rn(v.z, v.w);
    uint2 u;
    u.x = *reinterpret_cast<uint32_t*>(&a);
    u.y = *reinterpret_cast<uint32_t*>(&b);
    return u;
}

// accumulate 8 halfs (uint4) into two float4s
__device__ __forceinline__ void acc_h8(float4& a, float4& b, uint4 u) {
    __half2 h0 = *reinterpret_cast<__half2*>(&u.x);
    __half2 h1 = *reinterpret_cast<__half2*>(&u.y);
    __half2 h2 = *reinterpret_cast<__half2*>(&u.z);
    __half2 h3 = *reinterpret_cast<__half2*>(&u.w);
    float2 f0 = __half22float2(h0), f1 = __half22float2(h1);
    float2 f2 = __half22float2(h2), f3 = __half22float2(h3);
    a.x += f0.x; a.y += f0.y; a.z += f1.x; a.w += f1.y;
    b.x += f2.x; b.y += f2.y; b.z += f3.x; b.w += f3.y;
}

// ---------------------------------------------------------------------------
// u-space pull propagation: u_out[d] = scale2[d] * sum_{s in row(d)} u[s]
// D=128: 16 lanes per node, uint4 (8 halfs) per lane -> half the load
// instructions of the 32-lane/uint2 version; same bytes, same coalescing.
// ---------------------------------------------------------------------------
__global__ __launch_bounds__(256)
void prop_pull128(const __half* __restrict__ u, const float* __restrict__ scale2,
                  const int* __restrict__ rowptr, const int* __restrict__ csr,
                  __half* __restrict__ out, int N) {
    int t    = blockIdx.x * blockDim.x + threadIdx.x;
    int node = t >> 4;
    int lane = t & 15;
    if (node >= N) return;
    int beg = __ldg(rowptr + node), end = __ldg(rowptr + node + 1);
    const uint4* __restrict__ hv = reinterpret_cast<const uint4*>(u);  // 8 halfs each; 16/row
    float4 accA = make_float4(0.f, 0.f, 0.f, 0.f);
    float4 accB = make_float4(0.f, 0.f, 0.f, 0.f);
    int e = beg;
    for (; e + 4 <= end; e += 4) {
        int s0 = __ldg(csr + e), s1 = __ldg(csr + e + 1);
        int s2 = __ldg(csr + e + 2), s3 = __ldg(csr + e + 3);
        uint4 v0 = __ldg(hv + (size_t)s0 * 16 + lane);
        uint4 v1 = __ldg(hv + (size_t)s1 * 16 + lane);
        uint4 v2 = __ldg(hv + (size_t)s2 * 16 + lane);
        uint4 v3 = __ldg(hv + (size_t)s3 * 16 + lane);
        acc_h8(accA, accB, v0);
        acc_h8(accA, accB, v1);
        acc_h8(accA, accB, v2);
        acc_h8(accA, accB, v3);
    }
    for (; e < end; ++e) {
        int s = __ldg(csr + e);
        uint4 v = __ldg(hv + (size_t)s * 16 + lane);
        acc_h8(accA, accB, v);
    }
    float s2v = __ldg(scale2 + node);
    accA.x *= s2v; accA.y *= s2v; accA.z *= s2v; accA.w *= s2v;
    accB.x *= s2v; accB.y *= s2v; accB.z *= s2v; accB.w *= s2v;
    __half2 o0 = __floats2half2_rn(accA.x, accA.y);
    __half2 o1 = __floats2half2_rn(accA.z, accA.w);
    __half2 o2 = __floats2half2_rn(accB.x, accB.y);
    __half2 o3 = __floats2half2_rn(accB.z, accB.w);
    uint4 o;
    o.x = *reinterpret_cast<uint32_t*>(&o0);
    o.y = *reinterpret_cast<uint32_t*>(&o1);
    o.z = *reinterpret_cast<uint32_t*>(&o2);
    o.w = *reinterpret_cast<uint32_t*>(&o3);
    reinterpret_cast<uint4*>(out)[(size_t)node * 16 + lane] = o;
}

// D=32: 8 lanes per node, uint2 (R11-proven)
__global__ __launch_bounds__(256)
void prop_pull32(const __half* __restrict__ u, const float* __restrict__ scale2,
                 const int* __restrict__ rowptr, const int* __restrict__ csr,
                 __half* __restrict__ out, int N) {
    int t = blockIdx.x * blockDim.x + threadIdx.x;
    int node = t >> 3;
    int lane = t & 7;
    if (node >= N) return;
    int beg = __ldg(rowptr + node), end = __ldg(rowptr + node + 1);
    const uint2* __restrict__ hv = reinterpret_cast<const uint2*>(u);
    float4 acc = make_float4(0.f, 0.f, 0.f, 0.f);
    int e = beg;
    for (; e + 4 <= end; e += 4) {
        int s0 = __ldg(csr + e), s1 = __ldg(csr + e + 1);
        int s2 = __ldg(csr + e + 2), s3 = __ldg(csr + e + 3);
        float4 v0 = ld_h4(hv + (size_t)s0 * 8 + lane);
        float4 v1 = ld_h4(hv + (size_t)s1 * 8 + lane);
        float4 v2 = ld_h4(hv + (size_t)s2 * 8 + lane);
        float4 v3 = ld_h4(hv + (size_t)s3 * 8 + lane);
        acc.x += v0.x + v1.x + v2.x + v3.x;
        acc.y += v0.y + v1.y + v2.y + v3.y;
        acc.z += v0.z + v1.z + v2.z + v3.z;
        acc.w += v0.w + v1.w + v2.w + v3.w;
    }
    for (; e < end; ++e) {
        int s = __ldg(csr + e);
        float4 v = ld_h4(hv + (size_t)s * 8 + lane);
        acc.x += v.x; acc.y += v.y; acc.z += v.z; acc.w += v.w;
    }
    float s2v = __ldg(scale2 + node);
    acc.x *= s2v; acc.y *= s2v; acc.z *= s2v; acc.w *= s2v;
    reinterpret_cast<uint2*>(out)[(size_t)node * 8 + lane] = st_h4(acc);
}

// ---------------------------------------------------------------------------
// FP16 tensor-core fused GEMM, u-space aware (R11-proven):
// A rows are u-space -> scaled by rnh[row] (= 1/norm) at load.
// true_out = relu(concat @ W + b); epilogue writes norm[row]*true_out (fp16)
// when HALF_OUT (feeds next u-space prop) or plain fp32 for the final layer.
// ---------------------------------------------------------------------------
__device__ __forceinline__ void mma_f16(float c[4], const uint32_t a[4], const uint32_t b[2]) {
    asm volatile(
        "mma.sync.aligned.m16n8k16.row.col.f32.f16.f16.f32 "
        "{%0,%1,%2,%3}, {%4,%5,%6,%7}, {%8,%9}, {%0,%1,%2,%3};"
        : "+f"(c[0]), "+f"(c[1]), "+f"(c[2]), "+f"(c[3])
        : "r"(a[0]), "r"(a[1]), "r"(a[2]), "r"(a[3]), "r"(b[0]), "r"(b[1]));
}

template <int DIN, bool HALF_OUT>
__global__ __launch_bounds__(256)
void gemm3_fp16(const __half* __restrict__ H0, const __half* __restrict__ H1,
                const __half* __restrict__ H2, const float* __restrict__ W,
                const float* __restrict__ bias, const __half* __restrict__ rnh,
                const float* __restrict__ normf, void* __restrict__ outv, int N) {
    __shared__ __align__(16) __half2 As[16][132];   // [k-pair][m]
    __shared__ __align__(16) __half2 Bs[16][128];   // [k-pair][n]

    const int tid     = threadIdx.x;
    const int wid     = tid >> 5;
    const int lane    = tid & 31;
    const int warp_m  = wid & 3;
    const int warp_n  = wid >> 2;
    const int groupID = lane >> 2;
    const int tig     = lane & 3;
    const int m0      = blockIdx.x * 128;

    float c[2][8][4];
#pragma unroll
    for (int mt = 0; mt < 2; mt++)
#pragma unroll
        for (int nt = 0; nt < 8; nt++)
#pragma unroll
            for (int i = 0; i < 4; i++) c[mt][nt][i] = 0.0f;

    const __half* srcs[3] = {H0, H1, H2};

    const int aRow = tid >> 3;          // 0..31
    const int aCol = (tid & 7) * 4;     // 0..28 halfs
    const int bRow = tid >> 5;          // 0..7
    const int bCol = (tid & 31) * 4;    // 0..124

    for (int part = 0; part < 3; ++part) {
        const __half* __restrict__ Hp = srcs[part];
        for (int k0 = 0; k0 < DIN; k0 += 32) {
            // A tile: fp16 u-space rows, scaled by rnh[row] (HMUL2, no cvt)
#pragma unroll
            for (int r = 0; r < 4; ++r) {
                int row = m0 + r * 32 + aRow;
                uint2 u = make_uint2(0u, 0u);
                __half2 rn2 = __floats2half2_rn(0.f, 0.f);
                if (row < N) {
                    u = __ldg(reinterpret_cast<const uint2*>(
                        Hp + (size_t)row * DIN + k0 + aCol));
                    rn2 = __half2half2(__ldg(rnh + row));
                }
                As[(aCol >> 1) + 0][r * 32 + aRow] =
                    __hmul2(*reinterpret_cast<__half2*>(&u.x), rn2);
                As[(aCol >> 1) + 1][r * 32 + aRow] =
                    __hmul2(*reinterpret_cast<__half2*>(&u.y), rn2);
            }
            // B tile: 16 k-pairs x 128 n (fp32 W packed to half2 k-pairs)
#pragma unroll
            for (int r = 0; r < 2; ++r) {
                int p = r * 8 + bRow;   // k-pair 0..15
                const float* w0p = W + (size_t)(part * DIN + k0 + 2 * p) * 128 + bCol;
                float4 w0 = __ldg(reinterpret_cast<const float4*>(w0p));
                float4 w1 = __ldg(reinterpret_cast<const float4*>(w0p + 128));
                Bs[p][bCol + 0] = __floats2half2_rn(w0.x, w1.x);
                Bs[p][bCol + 1] = __floats2half2_rn(w0.y, w1.y);
                Bs[p][bCol + 2] = __floats2half2_rn(w0.z, w1.z);
                Bs[p][bCol + 3] = __floats2half2_rn(w0.w, w1.w);
            }
            __syncthreads();

#pragma unroll
            for (int kk = 0; kk < 2; ++kk) {
                const int kb = kk * 8;
                uint32_t a[2][4];
#pragma unroll
                for (int mt = 0; mt < 2; mt++) {
                    int m = warp_m * 32 + mt * 16 + groupID;
                    a[mt][0] = *reinterpret_cast<const uint32_t*>(&As[kb + tig][m]);
                    a[mt][1] = *reinterpret_cast<const uint32_t*>(&As[kb + tig][m + 8]);
                    a[mt][2] = *reinterpret_cast<const uint32_t*>(&As[kb + tig + 4][m]);
                    a[mt][3] = *reinterpret_cast<const uint32_t*>(&As[kb + tig + 4][m + 8]);
                }
                uint32_t b[8][2];
#pragma unroll
                for (int nt = 0; nt < 8; nt++) {
                    int n = warp_n * 64 + nt * 8 + groupID;
                    b[nt][0] = *reinterpret_cast<const uint32_t*>(&Bs[kb + tig][n]);
                    b[nt][1] = *reinterpret_cast<const uint32_t*>(&Bs[kb + tig + 4][n]);
                }
#pragma unroll
                for (int mt = 0; mt < 2; mt++)
#pragma unroll
                    for (int nt = 0; nt < 8; nt++)
                        mma_f16(c[mt][nt], a[mt], b[nt]);
            }
            __syncthreads();
        }
    }

    // epilogue: bias + relu (+ norm scale when writing u-space fp16)
#pragma unroll
    for (int mt = 0; mt < 2; mt++) {
        int row0 = m0 + warp_m * 32 + mt * 16 + groupID;
        int row1 = row0 + 8;
        float nr0 = 1.f, nr1 = 1.f;
        if (HALF_OUT) {
            if (row0 < N) nr0 = __ldg(normf + row0);
            if (row1 < N) nr1 = __ldg(normf + row1);
        }
#pragma unroll
        for (int nt = 0; nt < 8; nt++) {
            int col = warp_n * 64 + nt * 8 + tig * 2;
            float2 bv = __ldg(reinterpret_cast<const float2*>(bias + col));
            float2 o0, o1;
            o0.x = fmaxf(c[mt][nt][0] + bv.x, 0.f);
            o0.y = fmaxf(c[mt][nt][1] + bv.y, 0.f);
            o1.x = fmaxf(c[mt][nt][2] + bv.x, 0.f);
            o1.y = fmaxf(c[mt][nt][3] + bv.y, 0.f);
            if (HALF_OUT) {
                __half* out = reinterpret_cast<__half*>(outv);
                if (row0 < N) {
                    __half2 hh = __floats2half2_rn(o0.x * nr0, o0.y * nr0);
                    *reinterpret_cast<__half2*>(out + (size_t)row0 * 128 + col) = hh;
                }
                if (row1 < N) {
                    __half2 hh = __floats2half2_rn(o1.x * nr1, o1.y * nr1);
                    *reinterpret_cast<__half2*>(out + (size_t)row1 * 128 + col) = hh;
                }
            } else {
                float* out = reinterpret_cast<float*>(outv);
                if (row0 < N)
                    *reinterpret_cast<float2*>(out + (size_t)row0 * 128 + col) = o0;
                if (row1 < N)
                    *reinterpret_cast<float2*>(out + (size_t)row1 * 128 + col) = o1;
            }
        }
    }
}

// ---------------------------------------------------------------------------
// launch
// ---------------------------------------------------------------------------
extern "C" void kernel_launch(void* const* d_in, const int* in_sizes, int n_in,
                              void* d_out, int out_size) {
    const float* x   = (const float*)d_in[0];
    const int*   src = (const int*)d_in[1];
    const int*   dst = (const int*)d_in[2];
    const float* W1  = (const float*)d_in[3];
    const float* b1  = (const float*)d_in[4];
    const float* W2  = (const float*)d_in[5];
    const float* b2  = (const float*)d_in[6];
    const float* W3  = (const float*)d_in[7];
    const float* b3  = (const float*)d_in[8];
    float* out = (float*)d_out;

    const int N = in_sizes[0] / 32;
    const int E = in_sizes[1];

    float *p_norm, *p_scale2;
    __half *p_rnh, *p_xh, *p_t1, *p_t2, *p_h1, *p_h2;
    int *p_cnt, *p_rowptr, *p_cursor, *p_bsums, *p_csr;
    cudaGetSymbolAddress((void**)&p_norm,   g_norm);
    cudaGetSymbolAddress((void**)&p_scale2, g_scale2);
    cudaGetSymbolAddress((void**)&p_rnh,    g_rnh);
    cudaGetSymbolAddress((void**)&p_xh,     g_xh);
    cudaGetSymbolAddress((void**)&p_cnt,    g_cnt);
    cudaGetSymbolAddress((void**)&p_rowptr, g_rowptr);
    cudaGetSymbolAddress((void**)&p_cursor, g_cursor);
    cudaGetSymbolAddress((void**)&p_bsums,  g_bsums);
    cudaGetSymbolAddress((void**)&p_csr,    g_csr);
    cudaGetSymbolAddress((void**)&p_t1,     g_t1);
    cudaGetSymbolAddress((void**)&p_t2,     g_t2);
    cudaGetSymbolAddress((void**)&p_h1,     g_h1);
    cudaGetSymbolAddress((void**)&p_h2,     g_h2);

    const int TB = 256;
    const int nb = (N + 1023) / 1024;

    // degree + norm/scale2/rnh + CSR build (cnt re-zeroed by add_off)
    hist_kernel<<<(E + TB - 1) / TB, TB>>>(dst, E, p_cnt);
    scan_block<<<nb, 256>>>(p_cnt, p_rowptr, p_bsums, p_norm, p_scale2, p_rnh, N);
    add_off<<<nb, 256>>>(p_rowptr, p_cursor, p_cnt, p_bsums, N, E, nb);
    scatter_kernel<<<(E + TB - 1) / TB, TB>>>(src, dst, E, p_cursor, p_csr);

    // u0 = norm ⊙ x (fp16); needs norm from scan_block
    const int n4 = (N * 32) / 4;
    f2h_scale<<<(n4 + TB - 1) / TB, TB>>>(x, p_norm, p_xh, n4);

    const int g128 = (N * 16 + TB - 1) / TB;   // 16 lanes per node
    const int g32  = (N * 8 + TB - 1) / TB;    // 8 lanes per node
    const int gg   = (N + 127) / 128;

    // ---- layer 1 (din = 32) ----
    prop_pull32<<<g32, TB>>>(p_xh, p_scale2, p_rowptr, p_csr, p_t1, N);
    prop_pull32<<<g32, TB>>>(p_t1, p_scale2, p_rowptr, p_csr, p_t2, N);
    gemm3_fp16<32, true><<<gg, 256>>>(p_xh, p_t1, p_t2, W1, b1, p_rnh, p_norm, p_h1, N);

    // ---- layer 2 (din = 128) ----
    prop_pull128<<<g128, TB>>>(p_h1, p_scale2, p_rowptr, p_csr, p_t1, N);
    prop_pull128<<<g128, TB>>>(p_t1, p_scale2, p_rowptr, p_csr, p_t2, N);
    gemm3_fp16<128, true><<<gg, 256>>>(p_h1, p_t1, p_t2, W2, b2, p_rnh, p_norm, p_h2, N);

    // ---- layer 3 (din = 128) ----
    prop_pull128<<<g128, TB>>>(p_h2, p_scale2, p_rowptr, p_csr, p_t1, N);
    prop_pull128<<<g128, TB>>>(p_t1, p_scale2, p_rowptr, p_csr, p_t2, N);
    gemm3_fp16<128, false><<<gg, 256>>>(p_h2, p_t1, p_t2, W3, b3, p_rnh, p_norm, out, N);
}

// round 13
// speedup vs baseline: 1.7441x; 1.0094x over previous
#include <cuda_runtime.h>
#include <cuda_fp16.h>
#include <cstdint>

#define NMAX 100000
#define EMAX 1600000
#define HID  128

// Scratch (static device globals — allocation-free per harness rules).
// g_cnt zero-init at load; add_off re-zeros each run (graph-replay safe).
__device__ float  g_norm[NMAX];     // deg^-1/2
__device__ float  g_scale2[NMAX];   // deg^-1  (= norm^2)
__device__ __half g_rnh[NMAX];      // deg^+1/2 (= 1/norm), fp16
__device__ int    g_cnt[NMAX];
__device__ int    g_rowptr[NMAX + 1];
__device__ int    g_cursor[NMAX];
__device__ int    g_bsums[128];
__device__ int    g_csr[EMAX];
__device__ __half g_xh[(size_t)NMAX * 32];   // u0 = norm ⊙ x
__device__ __half g_t1[(size_t)NMAX * HID];
__device__ __half g_t2[(size_t)NMAX * HID];
__device__ __half g_h1[(size_t)NMAX * HID];
__device__ __half g_h2[(size_t)NMAX * HID];
// prepacked fp16 weights: rows of half2 pairs (W[2p][n], W[2p+1][n]), 128 half2/row
__device__ __half2 g_wp1[48][128];    // W1: 96 rows  -> 48 pair-rows
__device__ __half2 g_wp2[192][128];   // W2: 384 rows -> 192 pair-rows
__device__ __half2 g_wp3[192][128];   // W3: 384 rows -> 192 pair-rows

// ---------------------------------------------------------------------------
// weight prepack: W (rows x 128 fp32) -> Wp (rows/2 x 128 half2 k-pairs)
// ---------------------------------------------------------------------------
__global__ void pack_w(const float* __restrict__ W, __half2* __restrict__ Wp, int pairs) {
    int idx = blockIdx.x * blockDim.x + threadIdx.x;   // over pairs*32 groups of 4 cols
    if (idx >= pairs * 32) return;
    int kp  = idx >> 5;
    int c4  = (idx & 31) * 4;
    const float* w0 = W + (size_t)(2 * kp) * 128 + c4;
    float4 a = __ldg(reinterpret_cast<const float4*>(w0));
    float4 b = __ldg(reinterpret_cast<const float4*>(w0 + 128));
    __half2 p0 = __floats2half2_rn(a.x, b.x);
    __half2 p1 = __floats2half2_rn(a.y, b.y);
    __half2 p2 = __floats2half2_rn(a.z, b.z);
    __half2 p3 = __floats2half2_rn(a.w, b.w);
    uint4 o;
    o.x = *reinterpret_cast<uint32_t*>(&p0);
    o.y = *reinterpret_cast<uint32_t*>(&p1);
    o.z = *reinterpret_cast<uint32_t*>(&p2);
    o.w = *reinterpret_cast<uint32_t*>(&p3);
    *reinterpret_cast<uint4*>(Wp + (size_t)kp * 128 + c4) = o;
}

// ---------------------------------------------------------------------------
// degree histogram
// ---------------------------------------------------------------------------
__global__ void hist_kernel(const int* __restrict__ dst, int E, int* __restrict__ cnt) {
    int i = blockIdx.x * blockDim.x + threadIdx.x;
    if (i < E) atomicAdd(&cnt[dst[i]], 1);
}

// ---------------------------------------------------------------------------
// exclusive scan of cnt -> rowptr (1024 elems/block); also norm/scale2/rnh
// ---------------------------------------------------------------------------
__global__ void scan_block(const int* __restrict__ cnt, int* __restrict__ out,
                           int* __restrict__ bsums, float* __restrict__ norm,
                           float* __restrict__ scale2, __half* __restrict__ rnh, int N) {
    __shared__ int ss[256];
    const int tid  = threadIdx.x;
    const int base = blockIdx.x * 1024 + tid * 4;
    int local[4];
#pragma unroll
    for (int i = 0; i < 4; i++) {
        int g = base + i;
        local[i] = (g < N) ? cnt[g] : 0;
        if (g < N) {
            float d  = fmaxf((float)local[i], 1.0f);
            float nv = rsqrtf(d);
            norm[g]   = nv;
            scale2[g] = nv * nv;
            rnh[g]    = __float2half(sqrtf(d));
        }
    }
    int tsum = local[0] + local[1] + local[2] + local[3];
    ss[tid] = tsum;
    __syncthreads();
#pragma unroll
    for (int off = 1; off < 256; off <<= 1) {
        int v = (tid >= off) ? ss[tid - off] : 0;
        __syncthreads();
        ss[tid] += v;
        __syncthreads();
    }
    int run = ss[tid] - tsum;   // exclusive
#pragma unroll
    for (int i = 0; i < 4; i++) {
        int g = base + i;
        if (g < N) out[g] = run;
        run += local[i];
    }
    if (tid == 255) bsums[blockIdx.x] = ss[255];
}

// add block offsets (bsums prefix computed in-block), init cursor, re-zero cnt.
__global__ void add_off(int* __restrict__ rowptr, int* __restrict__ cursor,
                        int* __restrict__ cnt, const int* __restrict__ bsums,
                        int N, int E, int nb) {
    __shared__ int ss[256];
    const int tid = threadIdx.x;
    int v = (tid < nb && tid < blockIdx.x) ? bsums[tid] : 0;
    ss[tid] = v;
    __syncthreads();
#pragma unroll
    for (int off = 128; off > 0; off >>= 1) {
        if (tid < off) ss[tid] += ss[tid + off];
        __syncthreads();
    }
    const int o = ss[0];
    int g = blockIdx.x * 1024 + tid * 4;
#pragma unroll
    for (int i = 0; i < 4; i++) {
        if (g + i < N) {
            int val = rowptr[g + i] + o;
            rowptr[g + i] = val;
            cursor[g + i] = val;
            cnt[g + i]    = 0;
        }
    }
    if (blockIdx.x == 0 && tid == 0) rowptr[N] = E;
}

__global__ void scatter_kernel(const int* __restrict__ src, const int* __restrict__ dst,
                               int E, int* __restrict__ cursor, int* __restrict__ csr) {
    int e = blockIdx.x * blockDim.x + threadIdx.x;
    if (e < E) {
        int d = dst[e];
        int pos = atomicAdd(&cursor[d], 1);
        csr[pos] = src[e];
    }
}

// ---------------------------------------------------------------------------
// x (fp32) -> u0 = norm ⊙ x (fp16). Thread handles 4 floats; 8 float4s/row.
// ---------------------------------------------------------------------------
__global__ void f2h_scale(const float* __restrict__ x, const float* __restrict__ norm,
                          __half* __restrict__ u, int n4) {
    int i = blockIdx.x * blockDim.x + threadIdx.x;
    if (i < n4) {
        float nv = __ldg(norm + (i >> 3));
        float4 v = __ldg(reinterpret_cast<const float4*>(x) + i);
        __half2 a = __floats2half2_rn(v.x * nv, v.y * nv);
        __half2 b = __floats2half2_rn(v.z * nv, v.w * nv);
        uint2 o;
        o.x = *reinterpret_cast<uint32_t*>(&a);
        o.y = *reinterpret_cast<uint32_t*>(&b);
        reinterpret_cast<uint2*>(u)[i] = o;
    }
}

// ---------------------------------------------------------------------------
// fp16 helpers
// ---------------------------------------------------------------------------
// accumulate 8 halfs (uint4) into two float4s
__device__ __forceinline__ void acc_h8(float4& a, float4& b, uint4 u) {
    __half2 h0 = *reinterpret_cast<__half2*>(&u.x);
    __half2 h1 = *reinterpret_cast<__half2*>(&u.y);
    __half2 h2 = *reinterpret_cast<__half2*>(&u.z);
    __half2 h3 = *reinterpret_cast<__half2*>(&u.w);
    float2 f0 = __half22float2(h0), f1 = __half22float2(h1);
    float2 f2 = __half22float2(h2), f3 = __half22float2(h3);
    a.x += f0.x; a.y += f0.y; a.z += f1.x; a.w += f1.y;
    b.x += f2.x; b.y += f2.y; b.z += f3.x; b.w += f3.y;
}

__device__ __forceinline__ uint4 pack_h8(float4 a, float4 b, float s) {
    a.x *= s; a.y *= s; a.z *= s; a.w *= s;
    b.x *= s; b.y *= s; b.z *= s; b.w *= s;
    __half2 o0 = __floats2half2_rn(a.x, a.y);
    __half2 o1 = __floats2half2_rn(a.z, a.w);
    __half2 o2 = __floats2half2_rn(b.x, b.y);
    __half2 o3 = __floats2half2_rn(b.z, b.w);
    uint4 o;
    o.x = *reinterpret_cast<uint32_t*>(&o0);
    o.y = *reinterpret_cast<uint32_t*>(&o1);
    o.z = *reinterpret_cast<uint32_t*>(&o2);
    o.w = *reinterpret_cast<uint32_t*>(&o3);
    return o;
}

// ---------------------------------------------------------------------------
// u-space pull propagation: u_out[d] = scale2[d] * sum_{s in row(d)} u[s]
// D=128: 16 lanes per node, uint4 per lane (R12-proven).
// ---------------------------------------------------------------------------
__global__ __launch_bounds__(256)
void prop_pull128(const __half* __restrict__ u, const float* __restrict__ scale2,
                  const int* __restrict__ rowptr, const int* __restrict__ csr,
                  __half* __restrict__ out, int N) {
    int t    = blockIdx.x * blockDim.x + threadIdx.x;
    int node = t >> 4;
    int lane = t & 15;
    if (node >= N) return;
    int beg = __ldg(rowptr + node), end = __ldg(rowptr + node + 1);
    const uint4* __restrict__ hv = reinterpret_cast<const uint4*>(u);  // 16/row
    float4 accA = make_float4(0.f, 0.f, 0.f, 0.f);
    float4 accB = make_float4(0.f, 0.f, 0.f, 0.f);
    int e = beg;
    for (; e + 4 <= end; e += 4) {
        int s0 = __ldg(csr + e), s1 = __ldg(csr + e + 1);
        int s2 = __ldg(csr + e + 2), s3 = __ldg(csr + e + 3);
        uint4 v0 = __ldg(hv + (size_t)s0 * 16 + lane);
        uint4 v1 = __ldg(hv + (size_t)s1 * 16 + lane);
        uint4 v2 = __ldg(hv + (size_t)s2 * 16 + lane);
        uint4 v3 = __ldg(hv + (size_t)s3 * 16 + lane);
        acc_h8(accA, accB, v0);
        acc_h8(accA, accB, v1);
        acc_h8(accA, accB, v2);
        acc_h8(accA, accB, v3);
    }
    for (; e < end; ++e) {
        int s = __ldg(csr + e);
        uint4 v = __ldg(hv + (size_t)s * 16 + lane);
        acc_h8(accA, accB, v);
    }
    float s2v = __ldg(scale2 + node);
    reinterpret_cast<uint4*>(out)[(size_t)node * 16 + lane] = pack_h8(accA, accB, s2v);
}

// D=32: 4 lanes per node, uint4 per lane (R12 pattern applied)
__global__ __launch_bounds__(256)
void prop_pull32(const __half* __restrict__ u, const float* __restrict__ scale2,
                 const int* __restrict__ rowptr, const int* __restrict__ csr,
                 __half* __restrict__ out, int N) {
    int t    = blockIdx.x * blockDim.x + threadIdx.x;
    int node = t >> 2;
    int lane = t & 3;
    if (node >= N) return;
    int beg = __ldg(rowptr + node), end = __ldg(rowptr + node + 1);
    const uint4* __restrict__ hv = reinterpret_cast<const uint4*>(u);  // 4/row
    float4 accA = make_float4(0.f, 0.f, 0.f, 0.f);
    float4 accB = make_float4(0.f, 0.f, 0.f, 0.f);
    int e = beg;
    for (; e + 4 <= end; e += 4) {
        int s0 = __ldg(csr + e), s1 = __ldg(csr + e + 1);
        int s2 = __ldg(csr + e + 2), s3 = __ldg(csr + e + 3);
        uint4 v0 = __ldg(hv + (size_t)s0 * 4 + lane);
        uint4 v1 = __ldg(hv + (size_t)s1 * 4 + lane);
        uint4 v2 = __ldg(hv + (size_t)s2 * 4 + lane);
        uint4 v3 = __ldg(hv + (size_t)s3 * 4 + lane);
        acc_h8(accA, accB, v0);
        acc_h8(accA, accB, v1);
        acc_h8(accA, accB, v2);
        acc_h8(accA, accB, v3);
    }
    for (; e < end; ++e) {
        int s = __ldg(csr + e);
        uint4 v = __ldg(hv + (size_t)s * 4 + lane);
        acc_h8(accA, accB, v);
    }
    float s2v = __ldg(scale2 + node);
    reinterpret_cast<uint4*>(out)[(size_t)node * 4 + lane] = pack_h8(accA, accB, s2v);
}

// ---------------------------------------------------------------------------
// FP16 tensor-core fused GEMM, u-space aware, prepacked weights:
// A rows are u-space -> scaled by rnh[row] at load. B loads are single uint4
// ldg from the prepacked half2 k-pair layout (no cvt).
// ---------------------------------------------------------------------------
__device__ __forceinline__ void mma_f16(float c[4], const uint32_t a[4], const uint32_t b[2]) {
    asm volatile(
        "mma.sync.aligned.m16n8k16.row.col.f32.f16.f16.f32 "
        "{%0,%1,%2,%3}, {%4,%5,%6,%7}, {%8,%9}, {%0,%1,%2,%3};"
        : "+f"(c[0]), "+f"(c[1]), "+f"(c[2]), "+f"(c[3])
        : "r"(a[0]), "r"(a[1]), "r"(a[2]), "r"(a[3]), "r"(b[0]), "r"(b[1]));
}

template <int DIN, bool HALF_OUT>
__global__ __launch_bounds__(256)
void gemm3_fp16(const __half* __restrict__ H0, const __half* __restrict__ H1,
                const __half* __restrict__ H2, const __half2* __restrict__ Wp,
                const float* __restrict__ bias, const __half* __restrict__ rnh,
                const float* __restrict__ normf, void* __restrict__ outv, int N) {
    __shared__ __align__(16) __half2 As[16][132];   // [k-pair][m]
    __shared__ __align__(16) __half2 Bs[16][128];   // [k-pair][n]

    const int tid     = threadIdx.x;
    const int wid     = tid >> 5;
    const int lane    = tid & 31;
    const int warp_m  = wid & 3;
    const int warp_n  = wid >> 2;
    const int groupID = lane >> 2;
    const int tig     = lane & 3;
    const int m0      = blockIdx.x * 128;

    float c[2][8][4];
#pragma unroll
    for (int mt = 0; mt < 2; mt++)
#pragma unroll
        for (int nt = 0; nt < 8; nt++)
#pragma unroll
            for (int i = 0; i < 4; i++) c[mt][nt][i] = 0.0f;

    const __half* srcs[3] = {H0, H1, H2};

    const int aRow = tid >> 3;          // 0..31
    const int aCol = (tid & 7) * 4;     // 0..28 halfs
    const int bRow = tid >> 5;          // 0..7
    const int bCol = (tid & 31) * 4;    // 0..124

    for (int part = 0; part < 3; ++part) {
        const __half* __restrict__ Hp = srcs[part];
        for (int k0 = 0; k0 < DIN; k0 += 32) {
            // A tile: fp16 u-space rows, scaled by rnh[row] (HMUL2, no cvt)
#pragma unroll
            for (int r = 0; r < 4; ++r) {
                int row = m0 + r * 32 + aRow;
                uint2 u = make_uint2(0u, 0u);
                __half2 rn2 = __floats2half2_rn(0.f, 0.f);
                if (row < N) {
                    u = __ldg(reinterpret_cast<const uint2*>(
                        Hp + (size_t)row * DIN + k0 + aCol));
                    rn2 = __half2half2(__ldg(rnh + row));
                }
                As[(aCol >> 1) + 0][r * 32 + aRow] =
                    __hmul2(*reinterpret_cast<__half2*>(&u.x), rn2);
                As[(aCol >> 1) + 1][r * 32 + aRow] =
                    __hmul2(*reinterpret_cast<__half2*>(&u.y), rn2);
            }
            // B tile: 16 k-pairs x 128 n, single uint4 ldg from prepacked Wp
#pragma unroll
            for (int r = 0; r < 2; ++r) {
                int p = r * 8 + bRow;   // k-pair 0..15
                uint4 u = __ldg(reinterpret_cast<const uint4*>(
                    Wp + (size_t)((part * DIN) / 2 + (k0 >> 1) + p) * 128 + bCol));
                *reinterpret_cast<uint4*>(&Bs[p][bCol]) = u;
            }
            __syncthreads();

#pragma unroll
            for (int kk = 0; kk < 2; ++kk) {
                const int kb = kk * 8;
                uint32_t a[2][4];
#pragma unroll
                for (int mt = 0; mt < 2; mt++) {
                    int m = warp_m * 32 + mt * 16 + groupID;
                    a[mt][0] = *reinterpret_cast<const uint32_t*>(&As[kb + tig][m]);
                    a[mt][1] = *reinterpret_cast<const uint32_t*>(&As[kb + tig][m + 8]);
                    a[mt][2] = *reinterpret_cast<const uint32_t*>(&As[kb + tig + 4][m]);
                    a[mt][3] = *reinterpret_cast<const uint32_t*>(&As[kb + tig + 4][m + 8]);
                }
                uint32_t b[8][2];
#pragma unroll
                for (int nt = 0; nt < 8; nt++) {
                    int n = warp_n * 64 + nt * 8 + groupID;
                    b[nt][0] = *reinterpret_cast<const uint32_t*>(&Bs[kb + tig][n]);
                    b[nt][1] = *reinterpret_cast<const uint32_t*>(&Bs[kb + tig + 4][n]);
                }
#pragma unroll
                for (int mt = 0; mt < 2; mt++)
#pragma unroll
                    for (int nt = 0; nt < 8; nt++)
                        mma_f16(c[mt][nt], a[mt], b[nt]);
            }
            __syncthreads();
        }
    }

    // epilogue: bias + relu (+ norm scale when writing u-space fp16)
#pragma unroll
    for (int mt = 0; mt < 2; mt++) {
        int row0 = m0 + warp_m * 32 + mt * 16 + groupID;
        int row1 = row0 + 8;
        float nr0 = 1.f, nr1 = 1.f;
        if (HALF_OUT) {
            if (row0 < N) nr0 = __ldg(normf + row0);
            if (row1 < N) nr1 = __ldg(normf + row1);
        }
#pragma unroll
        for (int nt = 0; nt < 8; nt++) {
            int col = warp_n * 64 + nt * 8 + tig * 2;
            float2 bv = __ldg(reinterpret_cast<const float2*>(bias + col));
            float2 o0, o1;
            o0.x = fmaxf(c[mt][nt][0] + bv.x, 0.f);
            o0.y = fmaxf(c[mt][nt][1] + bv.y, 0.f);
            o1.x = fmaxf(c[mt][nt][2] + bv.x, 0.f);
            o1.y = fmaxf(c[mt][nt][3] + bv.y, 0.f);
            if (HALF_OUT) {
                __half* out = reinterpret_cast<__half*>(outv);
                if (row0 < N) {
                    __half2 hh = __floats2half2_rn(o0.x * nr0, o0.y * nr0);
                    *reinterpret_cast<__half2*>(out + (size_t)row0 * 128 + col) = hh;
                }
                if (row1 < N) {
                    __half2 hh = __floats2half2_rn(o1.x * nr1, o1.y * nr1);
                    *reinterpret_cast<__half2*>(out + (size_t)row1 * 128 + col) = hh;
                }
            } else {
                float* out = reinterpret_cast<float*>(outv);
                if (row0 < N)
                    *reinterpret_cast<float2*>(out + (size_t)row0 * 128 + col) = o0;
                if (row1 < N)
                    *reinterpret_cast<float2*>(out + (size_t)row1 * 128 + col) = o1;
            }
        }
    }
}

// ---------------------------------------------------------------------------
// launch
// ---------------------------------------------------------------------------
extern "C" void kernel_launch(void* const* d_in, const int* in_sizes, int n_in,
                              void* d_out, int out_size) {
    const float* x   = (const float*)d_in[0];
    const int*   src = (const int*)d_in[1];
    const int*   dst = (const int*)d_in[2];
    const float* W1  = (const float*)d_in[3];
    const float* b1  = (const float*)d_in[4];
    const float* W2  = (const float*)d_in[5];
    const float* b2  = (const float*)d_in[6];
    const float* W3  = (const float*)d_in[7];
    const float* b3  = (const float*)d_in[8];
    float* out = (float*)d_out;

    const int N = in_sizes[0] / 32;
    const int E = in_sizes[1];

    float *p_norm, *p_scale2;
    __half *p_rnh, *p_xh, *p_t1, *p_t2, *p_h1, *p_h2;
    __half2 *p_wp1, *p_wp2, *p_wp3;
    int *p_cnt, *p_rowptr, *p_cursor, *p_bsums, *p_csr;
    cudaGetSymbolAddress((void**)&p_norm,   g_norm);
    cudaGetSymbolAddress((void**)&p_scale2, g_scale2);
    cudaGetSymbolAddress((void**)&p_rnh,    g_rnh);
    cudaGetSymbolAddress((void**)&p_xh,     g_xh);
    cudaGetSymbolAddress((void**)&p_cnt,    g_cnt);
    cudaGetSymbolAddress((void**)&p_rowptr, g_rowptr);
    cudaGetSymbolAddress((void**)&p_cursor, g_cursor);
    cudaGetSymbolAddress((void**)&p_bsums,  g_bsums);
    cudaGetSymbolAddress((void**)&p_csr,    g_csr);
    cudaGetSymbolAddress((void**)&p_t1,     g_t1);
    cudaGetSymbolAddress((void**)&p_t2,     g_t2);
    cudaGetSymbolAddress((void**)&p_h1,     g_h1);
    cudaGetSymbolAddress((void**)&p_h2,     g_h2);
    cudaGetSymbolAddress((void**)&p_wp1,    g_wp1);
    cudaGetSymbolAddress((void**)&p_wp2,    g_wp2);
    cudaGetSymbolAddress((void**)&p_wp3,    g_wp3);

    const int TB = 256;
    const int nb = (N + 1023) / 1024;

    // weight prepack (one-shot per launch; tiny)
    pack_w<<<(48 * 32 + TB - 1) / TB, TB>>>(W1, p_wp1, 48);
    pack_w<<<(192 * 32 + TB - 1) / TB, TB>>>(W2, p_wp2, 192);
    pack_w<<<(192 * 32 + TB - 1) / TB, TB>>>(W3, p_wp3, 192);

    // degree + norm/scale2/rnh + CSR build (cnt re-zeroed by add_off)
    hist_kernel<<<(E + TB - 1) / TB, TB>>>(dst, E, p_cnt);
    scan_block<<<nb, 256>>>(p_cnt, p_rowptr, p_bsums, p_norm, p_scale2, p_rnh, N);
    add_off<<<nb, 256>>>(p_rowptr, p_cursor, p_cnt, p_bsums, N, E, nb);
    scatter_kernel<<<(E + TB - 1) / TB, TB>>>(src, dst, E, p_cursor, p_csr);

    // u0 = norm ⊙ x (fp16); needs norm from scan_block
    const int n4 = (N * 32) / 4;
    f2h_scale<<<(n4 + TB - 1) / TB, TB>>>(x, p_norm, p_xh, n4);

    const int g128 = (N * 16 + TB - 1) / TB;   // 16 lanes per node
    const int g32  = (N * 4 + TB - 1) / TB;    // 4 lanes per node
    const int gg   = (N + 127) / 128;

    // ---- layer 1 (din = 32) ----
    prop_pull32<<<g32, TB>>>(p_xh, p_scale2, p_rowptr, p_csr, p_t1, N);
    prop_pull32<<<g32, TB>>>(p_t1, p_scale2, p_rowptr, p_csr, p_t2, N);
    gemm3_fp16<32, true><<<gg, 256>>>(p_xh, p_t1, p_t2, p_wp1, b1, p_rnh, p_norm, p_h1, N);

    // ---- layer 2 (din = 128) ----
    prop_pull128<<<g128, TB>>>(p_h1, p_scale2, p_rowptr, p_csr, p_t1, N);
    prop_pull128<<<g128, TB>>>(p_t1, p_scale2, p_rowptr, p_csr, p_t2, N);
    gemm3_fp16<128, true><<<gg, 256>>>(p_h1, p_t1, p_t2, p_wp2, b2, p_rnh, p_norm, p_h2, N);

    // ---- layer 3 (din = 128) ----
    prop_pull128<<<g128, TB>>>(p_h2, p_scale2, p_rowptr, p_csr, p_t1, N);
    prop_pull128<<<g128, TB>>>(p_t1, p_scale2, p_rowptr, p_csr, p_t2, N);
    gemm3_fp16<128, false><<<gg, 256>>>(p_h2, p_t1, p_t2, p_wp3, b3, p_rnh, p_norm, out, N);
}

// round 15
// speedup vs baseline: 1.8041x; 1.0344x over previous
#include <cuda_runtime.h>
#include <cuda_fp16.h>
#include <cstdint>

#define NMAX 100000
#define EMAX 1600000
#define HID  128

// Scratch (static device globals — allocation-free per harness rules).
// g_cnt zero-init at load; add_off re-zeros each run (graph-replay safe).
__device__ float  g_norm[NMAX];     // deg^-1/2
__device__ float  g_scale2[NMAX];   // deg^-1  (= norm^2)
__device__ __half g_rnh[NMAX];      // deg^+1/2 (= 1/norm), fp16
__device__ int    g_cnt[NMAX];
__device__ int    g_rowptr[NMAX + 1];
__device__ int    g_cursor[NMAX];
__device__ int    g_bsums[128];
__device__ int    g_csr[EMAX];
__device__ __half g_xh[(size_t)NMAX * 32];   // u0 = norm ⊙ x
__device__ __half g_t1[(size_t)NMAX * HID];
__device__ __half g_t2[(size_t)NMAX * HID];
__device__ __half g_h1[(size_t)NMAX * HID];
__device__ __half g_h2[(size_t)NMAX * HID];
// prepacked fp16 weights: rows of half2 pairs (W[2p][n], W[2p+1][n]), 128 half2/row
__device__ __half2 g_wp1[48][128];    // W1: 96 rows  -> 48 pair-rows
__device__ __half2 g_wp2[192][128];   // W2: 384 rows -> 192 pair-rows
__device__ __half2 g_wp3[192][128];   // W3: 384 rows -> 192 pair-rows

// ---------------------------------------------------------------------------
// weight prepack, all three W in one launch (segmented)
// ---------------------------------------------------------------------------
__global__ void pack_w_all(const float* __restrict__ W1, const float* __restrict__ W2,
                           const float* __restrict__ W3,
                           __half2* __restrict__ Wp1, __half2* __restrict__ Wp2,
                           __half2* __restrict__ Wp3) {
    int idx = blockIdx.x * blockDim.x + threadIdx.x;   // 432 pair-rows * 32 col-groups
    if (idx >= 432 * 32) return;
    const float* W;
    __half2* Wp;
    int kp;
    if (idx < 48 * 32)       { W = W1; Wp = Wp1; kp = idx >> 5; }
    else if (idx < 240 * 32) { W = W2; Wp = Wp2; kp = (idx - 48 * 32) >> 5; }
    else                     { W = W3; Wp = Wp3; kp = (idx - 240 * 32) >> 5; }
    int c4 = (idx & 31) * 4;
    const float* w0 = W + (size_t)(2 * kp) * 128 + c4;
    float4 a = __ldg(reinterpret_cast<const float4*>(w0));
    float4 b = __ldg(reinterpret_cast<const float4*>(w0 + 128));
    __half2 p0 = __floats2half2_rn(a.x, b.x);
    __half2 p1 = __floats2half2_rn(a.y, b.y);
    __half2 p2 = __floats2half2_rn(a.z, b.z);
    __half2 p3 = __floats2half2_rn(a.w, b.w);
    uint4 o;
    o.x = *reinterpret_cast<uint32_t*>(&p0);
    o.y = *reinterpret_cast<uint32_t*>(&p1);
    o.z = *reinterpret_cast<uint32_t*>(&p2);
    o.w = *reinterpret_cast<uint32_t*>(&p3);
    *reinterpret_cast<uint4*>(Wp + (size_t)kp * 128 + c4) = o;
}

// ---------------------------------------------------------------------------
// degree histogram
// ---------------------------------------------------------------------------
__global__ void hist_kernel(const int* __restrict__ dst, int E, int* __restrict__ cnt) {
    int i = blockIdx.x * blockDim.x + threadIdx.x;
    if (i < E) atomicAdd(&cnt[dst[i]], 1);
}

// ---------------------------------------------------------------------------
// exclusive scan of cnt -> rowptr (1024 elems/block); also norm/scale2/rnh
// ---------------------------------------------------------------------------
__global__ void scan_block(const int* __restrict__ cnt, int* __restrict__ out,
                           int* __restrict__ bsums, float* __restrict__ norm,
                           float* __restrict__ scale2, __half* __restrict__ rnh, int N) {
    __shared__ int ss[256];
    const int tid  = threadIdx.x;
    const int base = blockIdx.x * 1024 + tid * 4;
    int local[4];
#pragma unroll
    for (int i = 0; i < 4; i++) {
        int g = base + i;
        local[i] = (g < N) ? cnt[g] : 0;
        if (g < N) {
            float d  = fmaxf((float)local[i], 1.0f);
            float nv = rsqrtf(d);
            norm[g]   = nv;
            scale2[g] = nv * nv;
            rnh[g]    = __float2half(sqrtf(d));
        }
    }
    int tsum = local[0] + local[1] + local[2] + local[3];
    ss[tid] = tsum;
    __syncthreads();
#pragma unroll
    for (int off = 1; off < 256; off <<= 1) {
        int v = (tid >= off) ? ss[tid - off] : 0;
        __syncthreads();
        ss[tid] += v;
        __syncthreads();
    }
    int run = ss[tid] - tsum;   // exclusive
#pragma unroll
    for (int i = 0; i < 4; i++) {
        int g = base + i;
        if (g < N) out[g] = run;
        run += local[i];
    }
    if (tid == 255) bsums[blockIdx.x] = ss[255];
}

// add block offsets (bsums prefix computed in-block), init cursor, re-zero cnt.
__global__ void add_off(int* __restrict__ rowptr, int* __restrict__ cursor,
                        int* __restrict__ cnt, const int* __restrict__ bsums,
                        int N, int E, int nb) {
    __shared__ int ss[256];
    const int tid = threadIdx.x;
    int v = (tid < nb && tid < blockIdx.x) ? bsums[tid] : 0;
    ss[tid] = v;
    __syncthreads();
#pragma unroll
    for (int off = 128; off > 0; off >>= 1) {
        if (tid < off) ss[tid] += ss[tid + off];
        __syncthreads();
    }
    const int o = ss[0];
    int g = blockIdx.x * 1024 + tid * 4;
#pragma unroll
    for (int i = 0; i < 4; i++) {
        if (g + i < N) {
            int val = rowptr[g + i] + o;
            rowptr[g + i] = val;
            cursor[g + i] = val;
            cnt[g + i]    = 0;
        }
    }
    if (blockIdx.x == 0 && tid == 0) rowptr[N] = E;
}

__global__ void scatter_kernel(const int* __restrict__ src, const int* __restrict__ dst,
                               int E, int* __restrict__ cursor, int* __restrict__ csr) {
    int e = blockIdx.x * blockDim.x + threadIdx.x;
    if (e < E) {
        int d = dst[e];
        int pos = atomicAdd(&cursor[d], 1);
        csr[pos] = src[e];
    }
}

// ---------------------------------------------------------------------------
// x (fp32) -> u0 = norm ⊙ x (fp16). Thread handles 4 floats; 8 float4s/row.
// ---------------------------------------------------------------------------
__global__ void f2h_scale(const float* __restrict__ x, const float* __restrict__ norm,
                          __half* __restrict__ u, int n4) {
    int i = blockIdx.x * blockDim.x + threadIdx.x;
    if (i < n4) {
        float nv = __ldg(norm + (i >> 3));
        float4 v = __ldg(reinterpret_cast<const float4*>(x) + i);
        __half2 a = __floats2half2_rn(v.x * nv, v.y * nv);
        __half2 b = __floats2half2_rn(v.z * nv, v.w * nv);
        uint2 o;
        o.x = *reinterpret_cast<uint32_t*>(&a);
        o.y = *reinterpret_cast<uint32_t*>(&b);
        reinterpret_cast<uint2*>(u)[i] = o;
    }
}

// ---------------------------------------------------------------------------
// fp16 helpers
// ---------------------------------------------------------------------------
__device__ __forceinline__ void acc_h8(float4& a, float4& b, uint4 u) {
    __half2 h0 = *reinterpret_cast<__half2*>(&u.x);
    __half2 h1 = *reinterpret_cast<__half2*>(&u.y);
    __half2 h2 = *reinterpret_cast<__half2*>(&u.z);
    __half2 h3 = *reinterpret_cast<__half2*>(&u.w);
    float2 f0 = __half22float2(h0), f1 = __half22float2(h1);
    float2 f2 = __half22float2(h2), f3 = __half22float2(h3);
    a.x += f0.x; a.y += f0.y; a.z += f1.x; a.w += f1.y;
    b.x += f2.x; b.y += f2.y; b.z += f3.x; b.w += f3.y;
}

__device__ __forceinline__ uint4 pack_h8(float4 a, float4 b, float s) {
    a.x *= s; a.y *= s; a.z *= s; a.w *= s;
    b.x *= s; b.y *= s; b.z *= s; b.w *= s;
    __half2 o0 = __floats2half2_rn(a.x, a.y);
    __half2 o1 = __floats2half2_rn(a.z, a.w);
    __half2 o2 = __floats2half2_rn(b.x, b.y);
    __half2 o3 = __floats2half2_rn(b.z, b.w);
    uint4 o;
    o.x = *reinterpret_cast<uint32_t*>(&o0);
    o.y = *reinterpret_cast<uint32_t*>(&o1);
    o.z = *reinterpret_cast<uint32_t*>(&o2);
    o.w = *reinterpret_cast<uint32_t*>(&o3);
    return o;
}

// ---------------------------------------------------------------------------
// u-space pull propagation: u_out[d] = scale2[d] * sum_{s in row(d)} u[s]
// D=128: 16 lanes per node, uint4 per lane (R12-proven).
// ---------------------------------------------------------------------------
__global__ __launch_bounds__(256)
void prop_pull128(const __half* __restrict__ u, const float* __restrict__ scale2,
                  const int* __restrict__ rowptr, const int* __restrict__ csr,
                  __half* __restrict__ out, int N) {
    int t    = blockIdx.x * blockDim.x + threadIdx.x;
    int node = t >> 4;
    int lane = t & 15;
    if (node >= N) return;
    int beg = __ldg(rowptr + node), end = __ldg(rowptr + node + 1);
    const uint4* __restrict__ hv = reinterpret_cast<const uint4*>(u);  // 16/row
    float4 accA = make_float4(0.f, 0.f, 0.f, 0.f);
    float4 accB = make_float4(0.f, 0.f, 0.f, 0.f);
    int e = beg;
    for (; e + 4 <= end; e += 4) {
        int s0 = __ldg(csr + e), s1 = __ldg(csr + e + 1);
        int s2 = __ldg(csr + e + 2), s3 = __ldg(csr + e + 3);
        uint4 v0 = __ldg(hv + (size_t)s0 * 16 + lane);
        uint4 v1 = __ldg(hv + (size_t)s1 * 16 + lane);
        uint4 v2 = __ldg(hv + (size_t)s2 * 16 + lane);
        uint4 v3 = __ldg(hv + (size_t)s3 * 16 + lane);
        acc_h8(accA, accB, v0);
        acc_h8(accA, accB, v1);
        acc_h8(accA, accB, v2);
        acc_h8(accA, accB, v3);
    }
    for (; e < end; ++e) {
        int s = __ldg(csr + e);
        uint4 v = __ldg(hv + (size_t)s * 16 + lane);
        acc_h8(accA, accB, v);
    }
    float s2v = __ldg(scale2 + node);
    reinterpret_cast<uint4*>(out)[(size_t)node * 16 + lane] = pack_h8(accA, accB, s2v);
}

// D=32: 4 lanes per node, uint4 per lane (R13-proven)
__global__ __launch_bounds__(256)
void prop_pull32(const __half* __restrict__ u, const float* __restrict__ scale2,
                 const int* __restrict__ rowptr, const int* __restrict__ csr,
                 __half* __restrict__ out, int N) {
    int t    = blockIdx.x * blockDim.x + threadIdx.x;
    int node = t >> 2;
    int lane = t & 3;
    if (node >= N) return;
    int beg = __ldg(rowptr + node), end = __ldg(rowptr + node + 1);
    const uint4* __restrict__ hv = reinterpret_cast<const uint4*>(u);  // 4/row
    float4 accA = make_float4(0.f, 0.f, 0.f, 0.f);
    float4 accB = make_float4(0.f, 0.f, 0.f, 0.f);
    int e = beg;
    for (; e + 4 <= end; e += 4) {
        int s0 = __ldg(csr + e), s1 = __ldg(csr + e + 1);
        int s2 = __ldg(csr + e + 2), s3 = __ldg(csr + e + 3);
        uint4 v0 = __ldg(hv + (size_t)s0 * 4 + lane);
        uint4 v1 = __ldg(hv + (size_t)s1 * 4 + lane);
        uint4 v2 = __ldg(hv + (size_t)s2 * 4 + lane);
        uint4 v3 = __ldg(hv + (size_t)s3 * 4 + lane);
        acc_h8(accA, accB, v0);
        acc_h8(accA, accB, v1);
        acc_h8(accA, accB, v2);
        acc_h8(accA, accB, v3);
    }
    for (; e < end; ++e) {
        int s = __ldg(csr + e);
        uint4 v = __ldg(hv + (size_t)s * 4 + lane);
        acc_h8(accA, accB, v);
    }
    float s2v = __ldg(scale2 + node);
    reinterpret_cast<uint4*>(out)[(size_t)node * 4 + lane] = pack_h8(accA, accB, s2v);
}

// ---------------------------------------------------------------------------
// FP16 tensor-core fused GEMM, u-space aware, prepacked weights, BK=64:
// out = relu(concat @ W + b), A scaled by rnh at load, epilogue scales by norm
// when writing fp16 u-space. BK = min(DIN, 64): halves sync rounds vs BK=32.
// ---------------------------------------------------------------------------
__device__ __forceinline__ void mma_f16(float c[4], const uint32_t a[4], const uint32_t b[2]) {
    asm volatile(
        "mma.sync.aligned.m16n8k16.row.col.f32.f16.f16.f32 "
        "{%0,%1,%2,%3}, {%4,%5,%6,%7}, {%8,%9}, {%0,%1,%2,%3};"
        : "+f"(c[0]), "+f"(c[1]), "+f"(c[2]), "+f"(c[3])
        : "r"(a[0]), "r"(a[1]), "r"(a[2]), "r"(a[3]), "r"(b[0]), "r"(b[1]));
}

template <int DIN, bool HALF_OUT>
__global__ __launch_bounds__(256)
void gemm3_fp16(const __half* __restrict__ H0, const __half* __restrict__ H1,
                const __half* __restrict__ H2, const __half2* __restrict__ Wp,
                const float* __restrict__ bias, const __half* __restrict__ rnh,
                const float* __restrict__ normf, void* __restrict__ outv, int N) {
    constexpr int BK  = (DIN >= 64) ? 64 : 32;   // k per tile
    constexpr int KP  = BK / 2;                  // k-pairs per tile
    constexpr int GPR = BK / 8;                  // uint4 groups per A row
    constexpr int ROWS_PER_PASS = 256 / GPR;     // A rows loaded per pass
    constexpr int APASS = 128 / ROWS_PER_PASS;   // passes to cover 128 rows
    constexpr int BITER = KP / 8;                // B r-iters (8 pair-rows each)

    __shared__ __align__(16) __half2 As[KP][132];   // [k-pair][m]
    __shared__ __align__(16) __half2 Bs[KP][128];   // [k-pair][n]

    const int tid     = threadIdx.x;
    const int wid     = tid >> 5;
    const int lane    = tid & 31;
    const int warp_m  = wid & 3;
    const int warp_n  = wid >> 2;
    const int groupID = lane >> 2;
    const int tig     = lane & 3;
    const int m0      = blockIdx.x * 128;

    float c[2][8][4];
#pragma unroll
    for (int mt = 0; mt < 2; mt++)
#pragma unroll
        for (int nt = 0; nt < 8; nt++)
#pragma unroll
            for (int i = 0; i < 4; i++) c[mt][nt][i] = 0.0f;

    const __half* srcs[3] = {H0, H1, H2};

    const int aRow  = tid / GPR;                 // row within pass
    const int aColH = (tid % GPR) * 8;           // half offset within row
    const int bRow  = tid >> 5;                  // 0..7
    const int bCol  = (tid & 31) * 4;            // 0..124

    for (int part = 0; part < 3; ++part) {
        const __half* __restrict__ Hp = srcs[part];
        for (int k0 = 0; k0 < DIN; k0 += BK) {
            // A tile: 128 rows x BK halfs, uint4 per thread per pass, rnh-scaled
#pragma unroll
            for (int r = 0; r < APASS; ++r) {
                int row = m0 + r * ROWS_PER_PASS + aRow;
                uint4 u = make_uint4(0u, 0u, 0u, 0u);
                __half2 rn2 = __floats2half2_rn(0.f, 0.f);
                if (row < N) {
                    u = __ldg(reinterpret_cast<const uint4*>(
                        Hp + (size_t)row * DIN + k0 + aColH));
                    rn2 = __half2half2(__ldg(rnh + row));
                }
                int m = r * ROWS_PER_PASS + aRow;
                int kp = aColH >> 1;
                As[kp + 0][m] = __hmul2(*reinterpret_cast<__half2*>(&u.x), rn2);
                As[kp + 1][m] = __hmul2(*reinterpret_cast<__half2*>(&u.y), rn2);
                As[kp + 2][m] = __hmul2(*reinterpret_cast<__half2*>(&u.z), rn2);
                As[kp + 3][m] = __hmul2(*reinterpret_cast<__half2*>(&u.w), rn2);
            }
            // B tile: KP pair-rows x 128 n, single uint4 ldg per r-iter
#pragma unroll
            for (int r = 0; r < BITER; ++r) {
                int p = r * 8 + bRow;   // k-pair 0..KP-1
                uint4 u = __ldg(reinterpret_cast<const uint4*>(
                    Wp + (size_t)((part * DIN) / 2 + (k0 >> 1) + p) * 128 + bCol));
                *reinterpret_cast<uint4*>(&Bs[p][bCol]) = u;
            }
            __syncthreads();

#pragma unroll
            for (int kk = 0; kk < KP / 8; ++kk) {
                const int kb = kk * 8;
                uint32_t a[2][4];
#pragma unroll
                for (int mt = 0; mt < 2; mt++) {
                    int m = warp_m * 32 + mt * 16 + groupID;
                    a[mt][0] = *reinterpret_cast<const uint32_t*>(&As[kb + tig][m]);
                    a[mt][1] = *reinterpret_cast<const uint32_t*>(&As[kb + tig][m + 8]);
                    a[mt][2] = *reinterpret_cast<const uint32_t*>(&As[kb + tig + 4][m]);
                    a[mt][3] = *reinterpret_cast<const uint32_t*>(&As[kb + tig + 4][m + 8]);
                }
                uint32_t b[8][2];
#pragma unroll
                for (int nt = 0; nt < 8; nt++) {
                    int n = warp_n * 64 + nt * 8 + groupID;
                    b[nt][0] = *reinterpret_cast<const uint32_t*>(&Bs[kb + tig][n]);
                    b[nt][1] = *reinterpret_cast<const uint32_t*>(&Bs[kb + tig + 4][n]);
                }
#pragma unroll
                for (int mt = 0; mt < 2; mt++)
#pragma unroll
                    for (int nt = 0; nt < 8; nt++)
                        mma_f16(c[mt][nt], a[mt], b[nt]);
            }
            __syncthreads();
        }
    }

    // epilogue: bias + relu (+ norm scale when writing u-space fp16)
#pragma unroll
    for (int mt = 0; mt < 2; mt++) {
        int row0 = m0 + warp_m * 32 + mt * 16 + groupID;
        int row1 = row0 + 8;
        float nr0 = 1.f, nr1 = 1.f;
        if (HALF_OUT) {
            if (row0 < N) nr0 = __ldg(normf + row0);
            if (row1 < N) nr1 = __ldg(normf + row1);
        }
#pragma unroll
        for (int nt = 0; nt < 8; nt++) {
            int col = warp_n * 64 + nt * 8 + tig * 2;
            float2 bv = __ldg(reinterpret_cast<const float2*>(bias + col));
            float2 o0, o1;
            o0.x = fmaxf(c[mt][nt][0] + bv.x, 0.f);
            o0.y = fmaxf(c[mt][nt][1] + bv.y, 0.f);
            o1.x = fmaxf(c[mt][nt][2] + bv.x, 0.f);
            o1.y = fmaxf(c[mt][nt][3] + bv.y, 0.f);
            if (HALF_OUT) {
                __half* out = reinterpret_cast<__half*>(outv);
                if (row0 < N) {
                    __half2 hh = __floats2half2_rn(o0.x * nr0, o0.y * nr0);
                    *reinterpret_cast<__half2*>(out + (size_t)row0 * 128 + col) = hh;
                }
                if (row1 < N) {
                    __half2 hh = __floats2half2_rn(o1.x * nr1, o1.y * nr1);
                    *reinterpret_cast<__half2*>(out + (size_t)row1 * 128 + col) = hh;
                }
            } else {
                float* out = reinterpret_cast<float*>(outv);
                if (row0 < N)
                    *reinterpret_cast<float2*>(out + (size_t)row0 * 128 + col) = o0;
                if (row1 < N)
                    *reinterpret_cast<float2*>(out + (size_t)row1 * 128 + col) = o1;
            }
        }
    }
}

// ---------------------------------------------------------------------------
// launch
// ---------------------------------------------------------------------------
extern "C" void kernel_launch(void* const* d_in, const int* in_sizes, int n_in,
                              void* d_out, int out_size) {
    const float* x   = (const float*)d_in[0];
    const int*   src = (const int*)d_in[1];
    const int*   dst = (const int*)d_in[2];
    const float* W1  = (const float*)d_in[3];
    const float* b1  = (const float*)d_in[4];
    const float* W2  = (const float*)d_in[5];
    const float* b2  = (const float*)d_in[6];
    const float* W3  = (const float*)d_in[7];
    const float* b3  = (const float*)d_in[8];
    float* out = (float*)d_out;

    const int N = in_sizes[0] / 32;
    const int E = in_sizes[1];

    float *p_norm, *p_scale2;
    __half *p_rnh, *p_xh, *p_t1, *p_t2, *p_h1, *p_h2;
    __half2 *p_wp1, *p_wp2, *p_wp3;
    int *p_cnt, *p_rowptr, *p_cursor, *p_bsums, *p_csr;
    cudaGetSymbolAddress((void**)&p_norm,   g_norm);
    cudaGetSymbolAddress((void**)&p_scale2, g_scale2);
    cudaGetSymbolAddress((void**)&p_rnh,    g_rnh);
    cudaGetSymbolAddress((void**)&p_xh,     g_xh);
    cudaGetSymbolAddress((void**)&p_cnt,    g_cnt);
    cudaGetSymbolAddress((void**)&p_rowptr, g_rowptr);
    cudaGetSymbolAddress((void**)&p_cursor, g_cursor);
    cudaGetSymbolAddress((void**)&p_bsums,  g_bsums);
    cudaGetSymbolAddress((void**)&p_csr,    g_csr);
    cudaGetSymbolAddress((void**)&p_t1,     g_t1);
    cudaGetSymbolAddress((void**)&p_t2,     g_t2);
    cudaGetSymbolAddress((void**)&p_h1,     g_h1);
    cudaGetSymbolAddress((void**)&p_h2,     g_h2);
    cudaGetSymbolAddress((void**)&p_wp1,    g_wp1);
    cudaGetSymbolAddress((void**)&p_wp2,    g_wp2);
    cudaGetSymbolAddress((void**)&p_wp3,    g_wp3);

    const int TB = 256;
    const int nb = (N + 1023) / 1024;

    // weight prepack (single launch)
    pack_w_all<<<(432 * 32 + TB - 1) / TB, TB>>>(W1, W2, W3, p_wp1, p_wp2, p_wp3);

    // degree + norm/scale2/rnh + CSR build (cnt re-zeroed by add_off)
    hist_kernel<<<(E + TB - 1) / TB, TB>>>(dst, E, p_cnt);
    scan_block<<<nb, 256>>>(p_cnt, p_rowptr, p_bsums, p_norm, p_scale2, p_rnh, N);
    add_off<<<nb, 256>>>(p_rowptr, p_cursor, p_cnt, p_bsums, N, E, nb);
    scatter_kernel<<<(E + TB - 1) / TB, TB>>>(src, dst, E, p_cursor, p_csr);

    // u0 = norm ⊙ x (fp16)
    const int n4 = (N * 32) / 4;
    f2h_scale<<<(n4 + TB - 1) / TB, TB>>>(x, p_norm, p_xh, n4);

    const int g128 = (N * 16 + TB - 1) / TB;   // 16 lanes per node
    const int g32  = (N * 4 + TB - 1) / TB;    // 4 lanes per node
    const int gg   = (N + 127) / 128;

    // ---- layer 1 (din = 32) ----
    prop_pull32<<<g32, TB>>>(p_xh, p_scale2, p_rowptr, p_csr, p_t1, N);
    prop_pull32<<<g32, TB>>>(p_t1, p_scale2, p_rowptr, p_csr, p_t2, N);
    gemm3_fp16<32, true><<<gg, 256>>>(p_xh, p_t1, p_t2, p_wp1, b1, p_rnh, p_norm, p_h1, N);

    // ---- layer 2 (din = 128) ----
    prop_pull128<<<g128, TB>>>(p_h1, p_scale2, p_rowptr, p_csr, p_t1, N);
    prop_pull128<<<g128, TB>>>(p_t1, p_scale2, p_rowptr, p_csr, p_t2, N);
    gemm3_fp16<128, true><<<gg, 256>>>(p_h1, p_t1, p_t2, p_wp2, b2, p_rnh, p_norm, p_h2, N);

    // ---- layer 3 (din = 128) ----
    prop_pull128<<<g128, TB>>>(p_h2, p_scale2, p_rowptr, p_csr, p_t1, N);
    prop_pull128<<<g128, TB>>>(p_t1, p_scale2, p_rowptr, p_csr, p_t2, N);
    gemm3_fp16<128, false><<<gg, 256>>>(p_h2, p_t1, p_t2, p_wp3, b3, p_rnh, p_norm, out, N);
}